// round 11
// baseline (speedup 1.0000x reference)
#include <cuda_runtime.h>
#include <math.h>

#define B_   4096
#define L_   50
#define K_   10
#define LI_  20
#define D_   64
#define C_   10
#define NIP1 50001

typedef unsigned long long ull;

// ---------------- scratch (static device globals; no allocation) -------------
__device__ float g_ju1[NIP1 * 256];   // gate-permuted x@Wih with all biases folded
__device__ float g_jv[NIP1 * D_];
__device__ float g_wc[74 * 256];      // (W1@Wih) gate-permuted
__device__ float g_bc[256];           // b1@Wih + bih + bhh, gate-permuted
__device__ float g_wi[192 * 128];     // interleaved (W2[k][c], W5[k][c])
__device__ float g_hu[B_ * D_];
__device__ float g_s1[K_ * B_];       // transposed [K][B]
__device__ float g_s2[K_ * B_];
__device__ float g_d1[K_ * B_];
__device__ float g_d2[K_ * B_];
__device__ float g_cs[4 * K_];
__device__ int   g_order[B_];

__device__ __forceinline__ float lrelu(float x) { return x >= 0.f ? x : 0.01f * x; }

// packed f32x2 fma (FFMA2) — only reachable via PTX
#define FMA2(d, a, b, c) \
    asm("fma.rn.f32x2 %0, %1, %2, %3;" : "=l"(d) : "l"(a), "l"(b), "l"(c))
#define PACK_DUP(d, x) \
    asm("mov.b64 %0, {%1, %1};" : "=l"(d) : "f"(x))
#define PACK2(d, lo, hi) \
    asm("mov.b64 %0, {%1, %2};" : "=l"(d) : "f"(lo), "f"(hi))
#define UNPACK2(lo, hi, p) \
    asm("mov.b64 {%0, %1}, %2;" : "=f"(lo), "=f"(hi) : "l"(p))

__device__ __forceinline__ float sigf(float x) {
    return __fdividef(1.f, 1.f + __expf(-x));
}
__device__ __forceinline__ float tanhf_fast(float x) {
    return 1.f - __fdividef(2.f, __expf(2.f * x) + 1.f);
}

// ============================================================================
// K0: combine Wc = W1@Wih (gate-permuted), bc; also build interleaved g_wi.
// ============================================================================
__global__ void k_combine(const float* __restrict__ W1, const float* __restrict__ b1,
                          const float* __restrict__ Wih, const float* __restrict__ bih,
                          const float* __restrict__ bhh,
                          const float* __restrict__ W2, const float* __restrict__ W5) {
    int k = blockIdx.x;
    int tid = threadIdx.x;
    if (k < 74) {
        int jp = tid;
        int c = jp >> 2, g = jp & 3;
        int j = c + 64 * g;
        float s = 0.f;
#pragma unroll
        for (int m = 0; m < 64; m++)
            s = fmaf(W1[k * 64 + m], __ldg(&Wih[m * 256 + j]), s);
        g_wc[k * 256 + jp] = s;
    } else if (k == 74) {
        int jp = tid;
        int c = jp >> 2, g = jp & 3;
        int j = c + 64 * g;
        float s = bih[j] + bhh[j];
#pragma unroll
        for (int m = 0; m < 64; m++)
            s = fmaf(b1[m], __ldg(&Wih[m * 256 + j]), s);
        g_bc[jp] = s;
    } else {
        int idx = (k - 75) * 256 + tid;    // 0 .. 192*128-1
        int kk = idx >> 7, j = idx & 127;
        int c = j >> 1;
        g_wi[idx] = (j & 1) ? W5[kk * 64 + c] : W2[kk * 64 + c];
    }
}

// ============================================================================
// K0b: counting sort of rows by u_items_mask, DESCENDING.
// ============================================================================
__global__ void k_sort(const int* __restrict__ mask) {
    __shared__ int cnt[64], off[64];
    int tid = threadIdx.x;
    if (tid < 64) cnt[tid] = 0;
    __syncthreads();
    for (int i = tid; i < B_; i += 1024) atomicAdd(&cnt[mask[i]], 1);
    __syncthreads();
    if (tid == 0) {
        int run = 0;
        for (int m = 50; m >= 1; m--) { off[m] = run; run += cnt[m]; }
    }
    __syncthreads();
    if (tid < 64) cnt[tid] = 0;
    __syncthreads();
    for (int i = tid; i < B_; i += 1024) {
        int m = mask[i];
        int pos = off[m] + atomicAdd(&cnt[m], 1);
        g_order[pos] = i;
    }
}

// ============================================================================
// K1: g_ju1 = x74 @ Wc + bc, g_jv = x74 @ W3 + b3. (validated)
// ============================================================================
#define PRE_SMEM (32 * 76 * 4)

__global__ void __launch_bounds__(256)
k_precompute(const float* __restrict__ item_emb, const float* __restrict__ i_class,
             const float* __restrict__ W3, const float* __restrict__ b3) {
    extern __shared__ float sm[];
    float* xs = sm;                  // 32*76

    int tid = threadIdx.x;
    int c = tid & 31, rgrp = tid >> 5;
    int row0 = blockIdx.x * 32;
    for (int i = tid; i < 32 * 74; i += 256) {
        int rr = i / 74, k = i % 74;
        int row = row0 + rr;
        float v = 0.f;
        if (row < NIP1) v = (k < 64) ? item_emb[row * 64 + k] : i_class[row * 10 + (k - 64)];
        xs[rr * 76 + k] = v;
    }
    __syncthreads();

    ull a[4][4], jv[4];
    {
        const ull* bp = (const ull*)&g_bc[8 * c];
        ull b0 = __ldg(bp), b1v = __ldg(bp + 1), b2v = __ldg(bp + 2), b3v = __ldg(bp + 3);
        ull jb = __ldg((const ull*)&b3[2 * c]);
#pragma unroll
        for (int r = 0; r < 4; r++) {
            a[r][0] = b0; a[r][1] = b1v; a[r][2] = b2v; a[r][3] = b3v;
            jv[r] = jb;
        }
    }
#pragma unroll 2
    for (int k = 0; k < 74; k++) {
        const ulonglong2* wp = (const ulonglong2*)&g_wc[k * 256 + 8 * c];
        ulonglong2 wa = __ldg(wp), wb = __ldg(wp + 1);
        ull w3v = __ldg((const ull*)&W3[k * 64 + 2 * c]);
#pragma unroll
        for (int r = 0; r < 4; r++) {
            float av = xs[(rgrp * 4 + r) * 76 + k];
            ull ad; PACK_DUP(ad, av);
            FMA2(a[r][0], ad, wa.x, a[r][0]);
            FMA2(a[r][1], ad, wa.y, a[r][1]);
            FMA2(a[r][2], ad, wb.x, a[r][2]);
            FMA2(a[r][3], ad, wb.y, a[r][3]);
            FMA2(jv[r], ad, w3v, jv[r]);
        }
    }
#pragma unroll
    for (int r = 0; r < 4; r++) {
        int row = row0 + rgrp * 4 + r;
        if (row < NIP1) {
            ull* o = (ull*)&g_ju1[row * 256 + 8 * c];
            o[0] = a[r][0]; o[1] = a[r][1]; o[2] = a[r][2]; o[3] = a[r][3];
            *(ull*)&g_jv[row * 64 + 2 * c] = jv[r];
        }
    }
}

// ============================================================================
// K2: 2-ROW WARP-AUTONOMOUS LSTM. 2048 sorted chunks of 2 rows; each warp
// owns a whole chunk (all 64 cells: lane -> cells {2l, 2l+1}), so h never
// leaves the warp. Static 2-band LPT: c1 = wid*148+b, c2 = 1184+(7-wid)*148+b.
// Per k: 2 LDS.128 (weight gate-PAIRS, no dups) + 1 LDS.64 (h both rows)
// + 2 h-dups + 8 FFMA2 -> fma-bound 1024 cyc/step (half of the 4-row design).
// Accumulation order over k unchanged -> bitwise-identical results.
// ============================================================================
#define LSTM_WFL (2*64*2 + 104)    // floats per warp region (hbuf x2 + idxs)
#define LSTM_SMEM ((64*256 + 8*LSTM_WFL) * 4)

__global__ void __launch_bounds__(256, 1)
k_lstm(const int* __restrict__ u_items, const int* __restrict__ u_items_mask,
       const float* __restrict__ Whh) {
    extern __shared__ float sm[];
    float* Wp = sm;                               // 64*256 gate-permuted Whh
    int wid = threadIdx.x >> 5, lane = threadIdx.x & 31;
    float* hbuf = Wp + 64 * 256 + wid * LSTM_WFL; // 2 x 64x2 (layout [cell][row])
    int*   idxs = (int*)(hbuf + 256);             // 2*50

    // stage gate-permuted Whh: Wp[k][cell*4+g] = Whh[k][cell + 64*g]
    for (int i = threadIdx.x; i < 64 * 256; i += 256) {
        int k = i >> 8, jp = i & 255;
        Wp[i] = Whh[k * 256 + (jp >> 2) + 64 * (jp & 3)];
    }
    __syncthreads();   // the only block-wide barrier

    int c1 = wid * 148 + blockIdx.x;              // 0..1183
    int c2 = 1184 + (7 - wid) * 148 + blockIdx.x; // covers 1184..2047 (clipped)

#pragma unroll 1
    for (int ci = 0; ci < 2; ci++) {
        int chunk = ci ? c2 : c1;
        if (chunk >= 2048) break;

        int rows[2], msk[2];
#pragma unroll
        for (int r = 0; r < 2; r++) {
            rows[r] = g_order[chunk * 2 + r];
            msk[r] = u_items_mask[rows[r]];
        }
        int maxm = msk[0];   // sorted desc -> first is max

        for (int i = lane; i < 100; i += 32) {
            int r = i / 50, t = i - r * 50;
            idxs[i] = u_items[rows[r] * 50 + t];
        }
        for (int i = lane; i < 256; i += 32) hbuf[i] = 0.f;   // h_{-1} = 0
        __syncwarp();

        float c_reg[2][2];
        c_reg[0][0] = 0.f; c_reg[0][1] = 0.f; c_reg[1][0] = 0.f; c_reg[1][1] = 0.f;

        // prefetch x-part (cells 2l,2l+1 = 8 floats at offset 8*lane) for t=0
        float4 p[2][2];
#pragma unroll
        for (int r = 0; r < 2; r++) {
            const float4* src = (const float4*)&g_ju1[idxs[r * 50] * 256 + lane * 8];
            p[r][0] = src[0]; p[r][1] = src[1];
        }

        const float* WpL = Wp + lane * 8;

        for (int t = 0; t < maxm; t++) {
            const float* hr = hbuf + (t & 1) * 128;
            float* hw = hbuf + ((t + 1) & 1) * 128;

            // acc[row][cell][gatepair] from prefetched x-part (+folded biases)
            ull acc[2][2][2];
#pragma unroll
            for (int r = 0; r < 2; r++) {
#pragma unroll
                for (int c = 0; c < 2; c++) {
                    PACK2(acc[r][c][0], p[r][c].x, p[r][c].y);
                    PACK2(acc[r][c][1], p[r][c].z, p[r][c].w);
                }
            }
            if (t + 1 < maxm) {
#pragma unroll
                for (int r = 0; r < 2; r++) {
                    const float4* src = (const float4*)&g_ju1[idxs[r * 50 + t + 1] * 256 + lane * 8];
                    p[r][0] = src[0]; p[r][1] = src[1];
                }
            }

            // h @ Whh, software-pipelined
            ulonglong2 nwa = *(const ulonglong2*)&WpL[0];      // cell 2l   (g0,g1),(g2,g3)
            ulonglong2 nwb = *(const ulonglong2*)&WpL[4];      // cell 2l+1
            float2 nhf = *(const float2*)&hr[0];               // h[k=0] rows 0,1
#pragma unroll 8
            for (int k = 0; k < 64; k++) {
                ulonglong2 wa = nwa, wb = nwb;
                float2 hf = nhf;
                int kn = (k + 1) & 63;
                nwa = *(const ulonglong2*)&WpL[kn * 256];
                nwb = *(const ulonglong2*)&WpL[kn * 256 + 4];
                nhf = *(const float2*)&hr[kn * 2];
                ull d0, d1;
                PACK_DUP(d0, hf.x);
                PACK_DUP(d1, hf.y);
                FMA2(acc[0][0][0], d0, wa.x, acc[0][0][0]);
                FMA2(acc[0][0][1], d0, wa.y, acc[0][0][1]);
                FMA2(acc[0][1][0], d0, wb.x, acc[0][1][0]);
                FMA2(acc[0][1][1], d0, wb.y, acc[0][1][1]);
                FMA2(acc[1][0][0], d1, wa.x, acc[1][0][0]);
                FMA2(acc[1][0][1], d1, wa.y, acc[1][0][1]);
                FMA2(acc[1][1][0], d1, wb.x, acc[1][1][0]);
                FMA2(acc[1][1][1], d1, wb.y, acc[1][1][1]);
            }

            // epilogue: 4 (row,cell) updates per lane
            float hval[2][2];
#pragma unroll
            for (int r = 0; r < 2; r++) {
#pragma unroll
                for (int c = 0; c < 2; c++) {
                    float gi, gf, gg, go;
                    UNPACK2(gi, gf, acc[r][c][0]);
                    UNPACK2(gg, go, acc[r][c][1]);
                    float cc = sigf(gf) * c_reg[r][c] + sigf(gi) * tanhf_fast(gg);
                    c_reg[r][c] = cc;
                    hval[r][c] = sigf(go) * tanhf_fast(cc);
                }
            }
            // h layout [cell][row]: lane's 4 values are contiguous at 4*lane
            float4 hv4;
            hv4.x = hval[0][0];   // cell 2l,   row 0
            hv4.y = hval[1][0];   // cell 2l,   row 1
            hv4.z = hval[0][1];   // cell 2l+1, row 0
            hv4.w = hval[1][1];   // cell 2l+1, row 1
            *(float4*)&hw[4 * lane] = hv4;

#pragma unroll
            for (int r = 0; r < 2; r++) {
                if (t == msk[r] - 1) {
                    float2 o; o.x = hval[r][0]; o.y = hval[r][1];
                    *(float2*)&g_hu[rows[r] * 64 + 2 * lane] = o;
                }
            }
            __syncwarp();
        }
    }
}

// ============================================================================
// K3: merged per-row user stage (round-9 validated).
// ============================================================================
#define USER_SMEM ((128 + 128 + 8*384) * 4)

__global__ void __launch_bounds__(256)
k_user(const int* __restrict__ users, const int* __restrict__ items,
       const int* __restrict__ u_frids, const int* __restrict__ u_frids_mask,
       const int* __restrict__ u_frids_items, const int* __restrict__ F_i,
       const float* __restrict__ user_emb, const float* __restrict__ item_emb,
       const float* __restrict__ b2,
       const float* __restrict__ W4, const float* __restrict__ b4,
       const float* __restrict__ b5,
       const float* __restrict__ W6, const float* __restrict__ b6,
       const float* __restrict__ lambdas) {
    extern __shared__ float sm[];
    float* W4s = sm;                 // 128
    float* W6s = W4s + 128;          // 128
    float* zz  = W6s + 128;          // 8 * 384

    int tid = threadIdx.x;
    if (tid < 128) W4s[tid] = W4[tid];
    else W6s[tid - 128] = W6[tid - 128];
    __syncthreads();

    int w = tid >> 5, lane = tid & 31;
    int row = blockIdx.x * 8 + w;
    int c0 = lane * 2;
    float l0 = lambdas[0], l1 = lambdas[1], l2 = lambdas[2], l3 = lambdas[3];
    float b4v = b4[0], b6v = b6[0];

    int usr = users[row], itm = items[row];
    float2 u2  = *(const float2*)(user_emb + usr * 64 + c0);
    float2 ie2 = *(const float2*)(item_emb + itm * 64 + c0);
    float2 hu2 = *(const float2*)(g_hu + row * 64 + c0);

    float px[K_], py[K_];
#pragma unroll
    for (int k = 0; k < K_; k++) { px[k] = 0.f; py[k] = 0.f; }
    const int* ip = u_frids_items + row * (K_ * LI_);
#pragma unroll
    for (int k = 0; k < K_; k++) {
#pragma unroll
        for (int li = 0; li < LI_; li++) {
            int idx = ip[k * LI_ + li];
            float2 j2 = *(const float2*)(g_jv + idx * 64 + c0);
            px[k] += j2.x; py[k] += j2.y;
        }
    }

    float du_p = u2.x * W4s[c0] + u2.y * W4s[c0 + 1];
    float at_p[K_];
#pragma unroll
    for (int k = 0; k < K_; k++) {
        int fid = u_frids[row * K_ + k];
        float2 v2 = *(const float2*)(user_emb + fid * 64 + c0);
        at_p[k] = v2.x * W4s[64 + c0] + v2.y * W4s[65 + c0];
    }
#pragma unroll
    for (int o = 16; o; o >>= 1) {
        du_p += __shfl_xor_sync(0xffffffffu, du_p, o);
#pragma unroll
        for (int k = 0; k < K_; k++) at_p[k] += __shfl_xor_sync(0xffffffffu, at_p[k], o);
    }
    int fm = u_frids_mask[row];
    float at[K_];
#pragma unroll
    for (int k = 0; k < K_; k++) at[k] = lrelu(du_p + at_p[k] + b4v);
    float mx = -1e30f;
#pragma unroll
    for (int k = 0; k < K_; k++) if (k < fm) mx = fmaxf(mx, at[k]);
    float se = 0.f, ev[K_];
#pragma unroll
    for (int k = 0; k < K_; k++) { ev[k] = (k < fm) ? __expf(at[k] - mx) : 0.f; se += ev[k]; }
    float inv = __fdividef(1.f, se * (float)fm);

    float sux = 0.f, suy = 0.f;
#pragma unroll
    for (int k = 0; k < K_; k++) {
        float wk = ev[k] * inv;
        sux = fmaf(wk, px[k], sux);
        suy = fmaf(wk, py[k], suy);
    }

    ull* z = (ull*)(zz + w * 384);
    PACK2(z[c0],       hu2.x, sux);
    PACK2(z[c0 + 1],   hu2.y, suy);
    PACK2(z[64 + c0],     ie2.x, ie2.x);
    PACK2(z[64 + c0 + 1], ie2.y, ie2.y);
    PACK2(z[128 + c0],     hu2.x * ie2.x, sux * ie2.x);
    PACK2(z[128 + c0 + 1], hu2.y * ie2.y, suy * ie2.y);
    __syncwarp();
    ull acc0, acc1;
    PACK2(acc0, b2[c0], b5[c0]);
    PACK2(acc1, b2[c0 + 1], b5[c0 + 1]);
    const ulonglong2* wip = (const ulonglong2*)&g_wi[4 * lane];
#pragma unroll 8
    for (int k = 0; k < 192; k++) {
        ull zk = z[k];
        ulonglong2 wv = __ldg(wip + k * 32);
        FMA2(acc0, zk, wv.x, acc0);
        FMA2(acc1, zk, wv.y, acc1);
    }
    float huix, suix, huiy, suiy;
    UNPACK2(huix, suix, acc0);
    UNPACK2(huiy, suiy, acc1);

    float zsx = l0 * hu2.x + l1 * huix + l2 * sux + l3 * suix;
    float zsy = l0 * hu2.y + l1 * huiy + l2 * suy + l3 * suiy;

    float di_p = ie2.x * W6s[c0] + ie2.y * W6s[c0 + 1];
#pragma unroll
    for (int o = 16; o; o >>= 1) di_p += __shfl_xor_sync(0xffffffffu, di_p, o);

#pragma unroll
    for (int s = 0; s < 2; s++) {
        float sp[K_], dp[K_];
#pragma unroll
        for (int k = 0; k < K_; k++) {
            int fi = F_i[(row * 2 + s) * K_ + k];
            float2 f2 = *(const float2*)(item_emb + fi * 64 + c0);
            sp[k] = f2.x * W6s[64 + c0] + f2.y * W6s[65 + c0];
            dp[k] = f2.x * zsx + f2.y * zsy;
        }
#pragma unroll
        for (int o = 16; o; o >>= 1) {
#pragma unroll
            for (int k = 0; k < K_; k++) {
                sp[k] += __shfl_xor_sync(0xffffffffu, sp[k], o);
                dp[k] += __shfl_xor_sync(0xffffffffu, dp[k], o);
            }
        }
        if (lane == 0) {
            float* spo = s ? g_s2 : g_s1;
            float* dpo = s ? g_d2 : g_d1;
#pragma unroll
            for (int k = 0; k < K_; k++) {
                spo[k * B_ + row] = lrelu(di_p + sp[k] + b6v);
                dpo[k * B_ + row] = dp[k];
            }
        }
    }
}

// ============================================================================
// K4: per-column softmax stats (online), coalesced [K][B].
// ============================================================================
__global__ void k_cstat() {
    int sel = blockIdx.x / K_;
    int k = blockIdx.x % K_;
    const float* s = (sel ? g_s2 : g_s1) + k * B_;
    __shared__ float rm[1024], rs[1024];
    int tid = threadIdx.x;
    float m = -1e30f, acc = 0.f;
    for (int i = tid; i < B_; i += 1024) {
        float x = s[i];
        float nm = fmaxf(m, x);
        acc = acc * __expf(m - nm) + __expf(x - nm);
        m = nm;
    }
    rm[tid] = m; rs[tid] = acc;
    __syncthreads();
    for (int o = 512; o; o >>= 1) {
        if (tid < o) {
            float m2 = rm[tid + o], s2v = rs[tid + o];
            float nm = fmaxf(rm[tid], m2);
            rs[tid] = rs[tid] * __expf(rm[tid] - nm) + s2v * __expf(m2 - nm);
            rm[tid] = nm;
        }
        __syncthreads();
    }
    if (tid == 0) { g_cs[sel * 2 * K_ + k] = rm[0]; g_cs[sel * 2 * K_ + K_ + k] = rs[0]; }
}

// ============================================================================
// K5: final S + sigmoid (coalesced [K][B] reads)
// ============================================================================
__global__ void k_final(const float* __restrict__ alpha, float* __restrict__ out) {
    int b = blockIdx.x * 256 + threadIdx.x;
    float a = alpha[0];
    float S1 = 0.f, S2 = 0.f;
#pragma unroll
    for (int k = 0; k < K_; k++) {
        S1 += __expf(g_s1[k * B_ + b] - g_cs[k]) / g_cs[K_ + k] * g_d1[k * B_ + b];
        S2 += __expf(g_s2[k * B_ + b] - g_cs[2 * K_ + k]) / g_cs[3 * K_ + k] * g_d2[k * B_ + b];
    }
    float S = a * S1 + (1.f - a) * S2;
    out[b] = __fdividef(1.f, 1.f + __expf(-S));
}

// ============================================================================
extern "C" void kernel_launch(void* const* d_in, const int* in_sizes, int n_in,
                              void* d_out, int out_size) {
    const int*   users        = (const int*)d_in[0];
    const int*   items        = (const int*)d_in[1];
    const int*   u_items      = (const int*)d_in[2];
    const int*   u_items_mask = (const int*)d_in[3];
    const int*   u_frids      = (const int*)d_in[4];
    const int*   u_frids_mask = (const int*)d_in[5];
    const int*   u_frids_items= (const int*)d_in[6];
    const int*   F_i          = (const int*)d_in[7];
    const float* user_emb     = (const float*)d_in[8];
    const float* item_emb     = (const float*)d_in[9];
    const float* i_class      = (const float*)d_in[10];
    const float* W1  = (const float*)d_in[11];
    const float* b1  = (const float*)d_in[12];
    const float* Wih = (const float*)d_in[13];
    const float* Whh = (const float*)d_in[14];
    const float* bih = (const float*)d_in[15];
    const float* bhh = (const float*)d_in[16];
    const float* W2  = (const float*)d_in[17];
    const float* b2  = (const float*)d_in[18];
    const float* W3  = (const float*)d_in[19];
    const float* b3  = (const float*)d_in[20];
    const float* W4  = (const float*)d_in[21];
    const float* b4  = (const float*)d_in[22];
    const float* W5  = (const float*)d_in[23];
    const float* b5  = (const float*)d_in[24];
    const float* W6  = (const float*)d_in[25];
    const float* b6  = (const float*)d_in[26];
    const float* alpha   = (const float*)d_in[27];
    const float* lambdas = (const float*)d_in[28];

    cudaFuncSetAttribute(k_precompute, cudaFuncAttributeMaxDynamicSharedMemorySize, PRE_SMEM);
    cudaFuncSetAttribute(k_lstm, cudaFuncAttributeMaxDynamicSharedMemorySize, LSTM_SMEM);
    cudaFuncSetAttribute(k_user, cudaFuncAttributeMaxDynamicSharedMemorySize, USER_SMEM);

    k_combine<<<171, 256>>>(W1, b1, Wih, bih, bhh, W2, W5);
    k_sort<<<1, 1024>>>(u_items_mask);
    k_precompute<<<(NIP1 + 31) / 32, 256, PRE_SMEM>>>(item_emb, i_class, W3, b3);
    k_lstm<<<148, 256, LSTM_SMEM>>>(u_items, u_items_mask, Whh);
    k_user<<<B_ / 8, 256, USER_SMEM>>>(users, items, u_frids, u_frids_mask,
                                       u_frids_items, F_i, user_emb, item_emb,
                                       b2, W4, b4, b5, W6, b6, lambdas);
    k_cstat<<<2 * K_, 1024>>>();
    k_final<<<B_ / 256, 256>>>(alpha, (float*)d_out);
}

// round 12
// speedup vs baseline: 1.4271x; 1.4271x over previous
#include <cuda_runtime.h>
#include <math.h>

#define B_   4096
#define L_   50
#define K_   10
#define LI_  20
#define D_   64
#define C_   10
#define NIP1 50001

typedef unsigned long long ull;

// ---------------- scratch (static device globals; no allocation) -------------
__device__ float g_ju1[NIP1 * 256];   // gate-permuted x@Wih with all biases folded
__device__ float g_jv[NIP1 * D_];
__device__ float g_wc[74 * 256];      // (W1@Wih) gate-permuted
__device__ float g_bc[256];           // b1@Wih + bih + bhh, gate-permuted
__device__ float g_wi[192 * 128];     // interleaved (W2[k][c], W5[k][c])
__device__ float g_hu[B_ * D_];
__device__ float g_s1[K_ * B_];       // transposed [K][B]
__device__ float g_s2[K_ * B_];
__device__ float g_d1[K_ * B_];
__device__ float g_d2[K_ * B_];
__device__ float g_cs[4 * K_];
__device__ int   g_order[B_];

__device__ __forceinline__ float lrelu(float x) { return x >= 0.f ? x : 0.01f * x; }

// packed f32x2 fma (FFMA2) — only reachable via PTX
#define FMA2(d, a, b, c) \
    asm("fma.rn.f32x2 %0, %1, %2, %3;" : "=l"(d) : "l"(a), "l"(b), "l"(c))
#define PACK_DUP(d, x) \
    asm("mov.b64 %0, {%1, %1};" : "=l"(d) : "f"(x))
#define PACK2(d, lo, hi) \
    asm("mov.b64 %0, {%1, %2};" : "=l"(d) : "f"(lo), "f"(hi))
#define UNPACK2(lo, hi, p) \
    asm("mov.b64 {%0, %1}, %2;" : "=f"(lo), "=f"(hi) : "l"(p))

__device__ __forceinline__ float sigf(float x) {
    return __fdividef(1.f, 1.f + __expf(-x));
}
__device__ __forceinline__ float tanhf_fast(float x) {
    return 1.f - __fdividef(2.f, __expf(2.f * x) + 1.f);
}

// ============================================================================
// K0: combine Wc = W1@Wih (gate-permuted), bc; also build interleaved g_wi.
// ============================================================================
__global__ void k_combine(const float* __restrict__ W1, const float* __restrict__ b1,
                          const float* __restrict__ Wih, const float* __restrict__ bih,
                          const float* __restrict__ bhh,
                          const float* __restrict__ W2, const float* __restrict__ W5) {
    int k = blockIdx.x;
    int tid = threadIdx.x;
    if (k < 74) {
        int jp = tid;
        int c = jp >> 2, g = jp & 3;
        int j = c + 64 * g;
        float s = 0.f;
#pragma unroll
        for (int m = 0; m < 64; m++)
            s = fmaf(W1[k * 64 + m], __ldg(&Wih[m * 256 + j]), s);
        g_wc[k * 256 + jp] = s;
    } else if (k == 74) {
        int jp = tid;
        int c = jp >> 2, g = jp & 3;
        int j = c + 64 * g;
        float s = bih[j] + bhh[j];
#pragma unroll
        for (int m = 0; m < 64; m++)
            s = fmaf(b1[m], __ldg(&Wih[m * 256 + j]), s);
        g_bc[jp] = s;
    } else {
        int idx = (k - 75) * 256 + tid;    // 0 .. 192*128-1
        int kk = idx >> 7, j = idx & 127;
        int c = j >> 1;
        g_wi[idx] = (j & 1) ? W5[kk * 64 + c] : W2[kk * 64 + c];
    }
}

// ============================================================================
// K0b: counting sort of rows by u_items_mask, DESCENDING.
// ============================================================================
__global__ void k_sort(const int* __restrict__ mask) {
    __shared__ int cnt[64], off[64];
    int tid = threadIdx.x;
    if (tid < 64) cnt[tid] = 0;
    __syncthreads();
    for (int i = tid; i < B_; i += 1024) atomicAdd(&cnt[mask[i]], 1);
    __syncthreads();
    if (tid == 0) {
        int run = 0;
        for (int m = 50; m >= 1; m--) { off[m] = run; run += cnt[m]; }
    }
    __syncthreads();
    if (tid < 64) cnt[tid] = 0;
    __syncthreads();
    for (int i = tid; i < B_; i += 1024) {
        int m = mask[i];
        int pos = off[m] + atomicAdd(&cnt[m], 1);
        g_order[pos] = i;
    }
}

// ============================================================================
// K1: g_ju1 = x74 @ Wc + bc, g_jv = x74 @ W3 + b3.
// NOW 64 rows/block, 8 rows/thread: halves per-row L1 weight traffic so it
// hides under the fma floor. Weights via __ldg (L1-resident).
// ============================================================================
#define PRE_SMEM (64 * 76 * 4)

__global__ void __launch_bounds__(256)
k_precompute(const float* __restrict__ item_emb, const float* __restrict__ i_class,
             const float* __restrict__ W3, const float* __restrict__ b3) {
    extern __shared__ float sm[];
    float* xs = sm;                  // 64*76

    int tid = threadIdx.x;
    int c = tid & 31, rgrp = tid >> 5;
    int row0 = blockIdx.x * 64;
    for (int i = tid; i < 64 * 74; i += 256) {
        int rr = i / 74, k = i % 74;
        int row = row0 + rr;
        float v = 0.f;
        if (row < NIP1) v = (k < 64) ? item_emb[row * 64 + k] : i_class[row * 10 + (k - 64)];
        xs[rr * 76 + k] = v;
    }
    __syncthreads();

    ull a[8][4], jv[8];
    {
        const ull* bp = (const ull*)&g_bc[8 * c];
        ull b0 = __ldg(bp), b1v = __ldg(bp + 1), b2v = __ldg(bp + 2), b3v = __ldg(bp + 3);
        ull jb = __ldg((const ull*)&b3[2 * c]);
#pragma unroll
        for (int r = 0; r < 8; r++) {
            a[r][0] = b0; a[r][1] = b1v; a[r][2] = b2v; a[r][3] = b3v;
            jv[r] = jb;
        }
    }
#pragma unroll 2
    for (int k = 0; k < 74; k++) {
        const ulonglong2* wp = (const ulonglong2*)&g_wc[k * 256 + 8 * c];
        ulonglong2 wa = __ldg(wp), wb = __ldg(wp + 1);
        ull w3v = __ldg((const ull*)&W3[k * 64 + 2 * c]);
        const float* xr = &xs[(rgrp * 8) * 76 + k];
#pragma unroll
        for (int r = 0; r < 8; r++) {
            float av = xr[r * 76];
            ull ad; PACK_DUP(ad, av);
            FMA2(a[r][0], ad, wa.x, a[r][0]);
            FMA2(a[r][1], ad, wa.y, a[r][1]);
            FMA2(a[r][2], ad, wb.x, a[r][2]);
            FMA2(a[r][3], ad, wb.y, a[r][3]);
            FMA2(jv[r], ad, w3v, jv[r]);
        }
    }
#pragma unroll
    for (int r = 0; r < 8; r++) {
        int row = row0 + rgrp * 8 + r;
        if (row < NIP1) {
            ull* o = (ull*)&g_ju1[row * 256 + 8 * c];
            o[0] = a[r][0]; o[1] = a[r][1]; o[2] = a[r][2]; o[3] = a[r][3];
            *(ull*)&g_jv[row * 64 + 2 * c] = jv[r];
        }
    }
}

// ============================================================================
// K2: WARP-AUTONOMOUS LSTM, 4 rows/warp, software-pipelined (ROUND-9
// VALIDATED, 113.5us). 4-row amortization keeps the smem crossbar under the
// fma floor (the 2-row variant doubled weight bytes/row and regressed 2x).
// ============================================================================
#define LSTM_WFL (2*64*4 + 200)    // floats per warp region (hbuf x2 + idxs)
#define LSTM_SMEM ((64*256 + 8*LSTM_WFL) * 4)

__global__ void __launch_bounds__(256, 1)
k_lstm(const int* __restrict__ u_items, const int* __restrict__ u_items_mask,
       const float* __restrict__ Whh) {
    extern __shared__ float sm[];
    float* Wp = sm;                               // 64*256
    int wid = threadIdx.x >> 5, lane = threadIdx.x & 31;
    float* hbuf = Wp + 64 * 256 + wid * LSTM_WFL; // 2 x 64x4
    int*   idxs = (int*)(hbuf + 2 * 64 * 4);      // 4*50

    // stage permuted Whh (even cells first half, odd cells second half)
    for (int i = threadIdx.x; i < 64 * 256; i += 256) {
        int k = i >> 8, jp = i & 255;
        int half = jp >> 7, rem = jp & 127;
        int l = rem >> 2, g = rem & 3;
        Wp[i] = Whh[k * 256 + (2 * l + half) + 64 * g];
    }
    __syncthreads();   // the only block-wide barrier

    int band = (wid < 4) ? wid : (11 - wid);      // pairs SMSP: (0,7)(1,6)(2,5)(3,4)
    int chunk = band * 148 + blockIdx.x;
    if (chunk >= 1024) return;

    int rows[4], msk[4];
#pragma unroll
    for (int r = 0; r < 4; r++) {
        rows[r] = g_order[chunk * 4 + r];
        msk[r] = u_items_mask[rows[r]];
    }
    int maxm = msk[0];    // sorted desc -> first is max

    for (int i = lane; i < 4 * 50; i += 32) {
        int r = i / 50, t = i - r * 50;
        idxs[i] = u_items[rows[r] * 50 + t];
    }
    for (int i = lane; i < 64 * 4; i += 32) hbuf[i] = 0.f;   // h_{-1} = 0
    __syncwarp();

    float c_reg[2][4];
#pragma unroll
    for (int c = 0; c < 2; c++)
#pragma unroll
        for (int r = 0; r < 4; r++) c_reg[c][r] = 0.f;

    float4 p[4][2];
#pragma unroll
    for (int r = 0; r < 4; r++) {
        const float4* src = (const float4*)&g_ju1[idxs[r * 50] * 256 + lane * 8];
        p[r][0] = src[0]; p[r][1] = src[1];
    }

    const float* WpA = Wp + lane * 4;
    const float* WpB = Wp + 128 + lane * 4;

    for (int t = 0; t < maxm; t++) {
        const float* hr = hbuf + (t & 1) * 256;
        float* hw = hbuf + ((t + 1) & 1) * 256;

        ull acc[2][4][2];
#pragma unroll
        for (int c = 0; c < 2; c++) {
            PACK2(acc[c][0][0], p[0][c].x, p[1][c].x);
            PACK2(acc[c][1][0], p[0][c].y, p[1][c].y);
            PACK2(acc[c][2][0], p[0][c].z, p[1][c].z);
            PACK2(acc[c][3][0], p[0][c].w, p[1][c].w);
            PACK2(acc[c][0][1], p[2][c].x, p[3][c].x);
            PACK2(acc[c][1][1], p[2][c].y, p[3][c].y);
            PACK2(acc[c][2][1], p[2][c].z, p[3][c].z);
            PACK2(acc[c][3][1], p[2][c].w, p[3][c].w);
        }
        if (t + 1 < maxm) {
#pragma unroll
            for (int r = 0; r < 4; r++) {
                const float4* src = (const float4*)&g_ju1[idxs[r * 50 + t + 1] * 256 + lane * 8];
                p[r][0] = src[0]; p[r][1] = src[1];
            }
        }

        float4 nwA = *(const float4*)&WpA[0];
        float4 nwB = *(const float4*)&WpB[0];
        ulonglong2 nhp = *(const ulonglong2*)&hr[0];
#pragma unroll 4
        for (int k = 0; k < 64; k++) {
            float4 wA = nwA, wB = nwB;
            ulonglong2 hp = nhp;
            int kn = (k + 1) & 63;
            nwA = *(const float4*)&WpA[kn * 256];
            nwB = *(const float4*)&WpB[kn * 256];
            nhp = *(const ulonglong2*)&hr[kn * 4];
            ull d;
            PACK_DUP(d, wA.x); FMA2(acc[0][0][0], hp.x, d, acc[0][0][0]); FMA2(acc[0][0][1], hp.y, d, acc[0][0][1]);
            PACK_DUP(d, wA.y); FMA2(acc[0][1][0], hp.x, d, acc[0][1][0]); FMA2(acc[0][1][1], hp.y, d, acc[0][1][1]);
            PACK_DUP(d, wA.z); FMA2(acc[0][2][0], hp.x, d, acc[0][2][0]); FMA2(acc[0][2][1], hp.y, d, acc[0][2][1]);
            PACK_DUP(d, wA.w); FMA2(acc[0][3][0], hp.x, d, acc[0][3][0]); FMA2(acc[0][3][1], hp.y, d, acc[0][3][1]);
            PACK_DUP(d, wB.x); FMA2(acc[1][0][0], hp.x, d, acc[1][0][0]); FMA2(acc[1][0][1], hp.y, d, acc[1][0][1]);
            PACK_DUP(d, wB.y); FMA2(acc[1][1][0], hp.x, d, acc[1][1][0]); FMA2(acc[1][1][1], hp.y, d, acc[1][1][1]);
            PACK_DUP(d, wB.z); FMA2(acc[1][2][0], hp.x, d, acc[1][2][0]); FMA2(acc[1][2][1], hp.y, d, acc[1][2][1]);
            PACK_DUP(d, wB.w); FMA2(acc[1][3][0], hp.x, d, acc[1][3][0]); FMA2(acc[1][3][1], hp.y, d, acc[1][3][1]);
        }

        float hval[2][4];
#pragma unroll
        for (int c = 0; c < 2; c++) {
#pragma unroll
            for (int pr = 0; pr < 2; pr++) {
                float gi0, gi1, gf0, gf1, gg0, gg1, go0, go1;
                UNPACK2(gi0, gi1, acc[c][0][pr]);
                UNPACK2(gf0, gf1, acc[c][1][pr]);
                UNPACK2(gg0, gg1, acc[c][2][pr]);
                UNPACK2(go0, go1, acc[c][3][pr]);
#pragma unroll
                for (int h2 = 0; h2 < 2; h2++) {
                    int r = 2 * pr + h2;
                    float gi = h2 ? gi1 : gi0;
                    float gf = h2 ? gf1 : gf0;
                    float gg = h2 ? gg1 : gg0;
                    float go = h2 ? go1 : go0;
                    float cc = sigf(gf) * c_reg[c][r] + sigf(gi) * tanhf_fast(gg);
                    c_reg[c][r] = cc;
                    hval[c][r] = sigf(go) * tanhf_fast(cc);
                }
                ull hp2; PACK2(hp2, hval[c][2 * pr], hval[c][2 * pr + 1]);
                *(ull*)&hw[(2 * lane + c) * 4 + 2 * pr] = hp2;
            }
        }
#pragma unroll
        for (int r = 0; r < 4; r++) {
            if (t == msk[r] - 1) {
                float2 o; o.x = hval[0][r]; o.y = hval[1][r];
                *(float2*)&g_hu[rows[r] * 64 + 2 * lane] = o;
            }
        }
        __syncwarp();
    }
}

// ============================================================================
// K3: merged per-row user stage (validated).
// ============================================================================
#define USER_SMEM ((128 + 128 + 8*384) * 4)

__global__ void __launch_bounds__(256)
k_user(const int* __restrict__ users, const int* __restrict__ items,
       const int* __restrict__ u_frids, const int* __restrict__ u_frids_mask,
       const int* __restrict__ u_frids_items, const int* __restrict__ F_i,
       const float* __restrict__ user_emb, const float* __restrict__ item_emb,
       const float* __restrict__ b2,
       const float* __restrict__ W4, const float* __restrict__ b4,
       const float* __restrict__ b5,
       const float* __restrict__ W6, const float* __restrict__ b6,
       const float* __restrict__ lambdas) {
    extern __shared__ float sm[];
    float* W4s = sm;                 // 128
    float* W6s = W4s + 128;          // 128
    float* zz  = W6s + 128;          // 8 * 384

    int tid = threadIdx.x;
    if (tid < 128) W4s[tid] = W4[tid];
    else W6s[tid - 128] = W6[tid - 128];
    __syncthreads();

    int w = tid >> 5, lane = tid & 31;
    int row = blockIdx.x * 8 + w;
    int c0 = lane * 2;
    float l0 = lambdas[0], l1 = lambdas[1], l2 = lambdas[2], l3 = lambdas[3];
    float b4v = b4[0], b6v = b6[0];

    int usr = users[row], itm = items[row];
    float2 u2  = *(const float2*)(user_emb + usr * 64 + c0);
    float2 ie2 = *(const float2*)(item_emb + itm * 64 + c0);
    float2 hu2 = *(const float2*)(g_hu + row * 64 + c0);

    float px[K_], py[K_];
#pragma unroll
    for (int k = 0; k < K_; k++) { px[k] = 0.f; py[k] = 0.f; }
    const int* ip = u_frids_items + row * (K_ * LI_);
#pragma unroll
    for (int k = 0; k < K_; k++) {
#pragma unroll
        for (int li = 0; li < LI_; li++) {
            int idx = ip[k * LI_ + li];
            float2 j2 = *(const float2*)(g_jv + idx * 64 + c0);
            px[k] += j2.x; py[k] += j2.y;
        }
    }

    float du_p = u2.x * W4s[c0] + u2.y * W4s[c0 + 1];
    float at_p[K_];
#pragma unroll
    for (int k = 0; k < K_; k++) {
        int fid = u_frids[row * K_ + k];
        float2 v2 = *(const float2*)(user_emb + fid * 64 + c0);
        at_p[k] = v2.x * W4s[64 + c0] + v2.y * W4s[65 + c0];
    }
#pragma unroll
    for (int o = 16; o; o >>= 1) {
        du_p += __shfl_xor_sync(0xffffffffu, du_p, o);
#pragma unroll
        for (int k = 0; k < K_; k++) at_p[k] += __shfl_xor_sync(0xffffffffu, at_p[k], o);
    }
    int fm = u_frids_mask[row];
    float at[K_];
#pragma unroll
    for (int k = 0; k < K_; k++) at[k] = lrelu(du_p + at_p[k] + b4v);
    float mx = -1e30f;
#pragma unroll
    for (int k = 0; k < K_; k++) if (k < fm) mx = fmaxf(mx, at[k]);
    float se = 0.f, ev[K_];
#pragma unroll
    for (int k = 0; k < K_; k++) { ev[k] = (k < fm) ? __expf(at[k] - mx) : 0.f; se += ev[k]; }
    float inv = __fdividef(1.f, se * (float)fm);

    float sux = 0.f, suy = 0.f;
#pragma unroll
    for (int k = 0; k < K_; k++) {
        float wk = ev[k] * inv;
        sux = fmaf(wk, px[k], sux);
        suy = fmaf(wk, py[k], suy);
    }

    ull* z = (ull*)(zz + w * 384);
    PACK2(z[c0],       hu2.x, sux);
    PACK2(z[c0 + 1],   hu2.y, suy);
    PACK2(z[64 + c0],     ie2.x, ie2.x);
    PACK2(z[64 + c0 + 1], ie2.y, ie2.y);
    PACK2(z[128 + c0],     hu2.x * ie2.x, sux * ie2.x);
    PACK2(z[128 + c0 + 1], hu2.y * ie2.y, suy * ie2.y);
    __syncwarp();
    ull acc0, acc1;
    PACK2(acc0, b2[c0], b5[c0]);
    PACK2(acc1, b2[c0 + 1], b5[c0 + 1]);
    const ulonglong2* wip = (const ulonglong2*)&g_wi[4 * lane];
#pragma unroll 8
    for (int k = 0; k < 192; k++) {
        ull zk = z[k];
        ulonglong2 wv = __ldg(wip + k * 32);
        FMA2(acc0, zk, wv.x, acc0);
        FMA2(acc1, zk, wv.y, acc1);
    }
    float huix, suix, huiy, suiy;
    UNPACK2(huix, suix, acc0);
    UNPACK2(huiy, suiy, acc1);

    float zsx = l0 * hu2.x + l1 * huix + l2 * sux + l3 * suix;
    float zsy = l0 * hu2.y + l1 * huiy + l2 * suy + l3 * suiy;

    float di_p = ie2.x * W6s[c0] + ie2.y * W6s[c0 + 1];
#pragma unroll
    for (int o = 16; o; o >>= 1) di_p += __shfl_xor_sync(0xffffffffu, di_p, o);

#pragma unroll
    for (int s = 0; s < 2; s++) {
        float sp[K_], dp[K_];
#pragma unroll
        for (int k = 0; k < K_; k++) {
            int fi = F_i[(row * 2 + s) * K_ + k];
            float2 f2 = *(const float2*)(item_emb + fi * 64 + c0);
            sp[k] = f2.x * W6s[64 + c0] + f2.y * W6s[65 + c0];
            dp[k] = f2.x * zsx + f2.y * zsy;
        }
#pragma unroll
        for (int o = 16; o; o >>= 1) {
#pragma unroll
            for (int k = 0; k < K_; k++) {
                sp[k] += __shfl_xor_sync(0xffffffffu, sp[k], o);
                dp[k] += __shfl_xor_sync(0xffffffffu, dp[k], o);
            }
        }
        if (lane == 0) {
            float* spo = s ? g_s2 : g_s1;
            float* dpo = s ? g_d2 : g_d1;
#pragma unroll
            for (int k = 0; k < K_; k++) {
                spo[k * B_ + row] = lrelu(di_p + sp[k] + b6v);
                dpo[k * B_ + row] = dp[k];
            }
        }
    }
}

// ============================================================================
// K4: per-column softmax stats (online), coalesced [K][B].
// ============================================================================
__global__ void k_cstat() {
    int sel = blockIdx.x / K_;
    int k = blockIdx.x % K_;
    const float* s = (sel ? g_s2 : g_s1) + k * B_;
    __shared__ float rm[1024], rs[1024];
    int tid = threadIdx.x;
    float m = -1e30f, acc = 0.f;
    for (int i = tid; i < B_; i += 1024) {
        float x = s[i];
        float nm = fmaxf(m, x);
        acc = acc * __expf(m - nm) + __expf(x - nm);
        m = nm;
    }
    rm[tid] = m; rs[tid] = acc;
    __syncthreads();
    for (int o = 512; o; o >>= 1) {
        if (tid < o) {
            float m2 = rm[tid + o], s2v = rs[tid + o];
            float nm = fmaxf(rm[tid], m2);
            rs[tid] = rs[tid] * __expf(rm[tid] - nm) + s2v * __expf(m2 - nm);
            rm[tid] = nm;
        }
        __syncthreads();
    }
    if (tid == 0) { g_cs[sel * 2 * K_ + k] = rm[0]; g_cs[sel * 2 * K_ + K_ + k] = rs[0]; }
}

// ============================================================================
// K5: final S + sigmoid (coalesced [K][B] reads)
// ============================================================================
__global__ void k_final(const float* __restrict__ alpha, float* __restrict__ out) {
    int b = blockIdx.x * 256 + threadIdx.x;
    float a = alpha[0];
    float S1 = 0.f, S2 = 0.f;
#pragma unroll
    for (int k = 0; k < K_; k++) {
        S1 += __expf(g_s1[k * B_ + b] - g_cs[k]) / g_cs[K_ + k] * g_d1[k * B_ + b];
        S2 += __expf(g_s2[k * B_ + b] - g_cs[2 * K_ + k]) / g_cs[3 * K_ + k] * g_d2[k * B_ + b];
    }
    float S = a * S1 + (1.f - a) * S2;
    out[b] = __fdividef(1.f, 1.f + __expf(-S));
}

// ============================================================================
extern "C" void kernel_launch(void* const* d_in, const int* in_sizes, int n_in,
                              void* d_out, int out_size) {
    const int*   users        = (const int*)d_in[0];
    const int*   items        = (const int*)d_in[1];
    const int*   u_items      = (const int*)d_in[2];
    const int*   u_items_mask = (const int*)d_in[3];
    const int*   u_frids      = (const int*)d_in[4];
    const int*   u_frids_mask = (const int*)d_in[5];
    const int*   u_frids_items= (const int*)d_in[6];
    const int*   F_i          = (const int*)d_in[7];
    const float* user_emb     = (const float*)d_in[8];
    const float* item_emb     = (const float*)d_in[9];
    const float* i_class      = (const float*)d_in[10];
    const float* W1  = (const float*)d_in[11];
    const float* b1  = (const float*)d_in[12];
    const float* Wih = (const float*)d_in[13];
    const float* Whh = (const float*)d_in[14];
    const float* bih = (const float*)d_in[15];
    const float* bhh = (const float*)d_in[16];
    const float* W2  = (const float*)d_in[17];
    const float* b2  = (const float*)d_in[18];
    const float* W3  = (const float*)d_in[19];
    const float* b3  = (const float*)d_in[20];
    const float* W4  = (const float*)d_in[21];
    const float* b4  = (const float*)d_in[22];
    const float* W5  = (const float*)d_in[23];
    const float* b5  = (const float*)d_in[24];
    const float* W6  = (const float*)d_in[25];
    const float* b6  = (const float*)d_in[26];
    const float* alpha   = (const float*)d_in[27];
    const float* lambdas = (const float*)d_in[28];

    cudaFuncSetAttribute(k_precompute, cudaFuncAttributeMaxDynamicSharedMemorySize, PRE_SMEM);
    cudaFuncSetAttribute(k_lstm, cudaFuncAttributeMaxDynamicSharedMemorySize, LSTM_SMEM);
    cudaFuncSetAttribute(k_user, cudaFuncAttributeMaxDynamicSharedMemorySize, USER_SMEM);

    k_combine<<<171, 256>>>(W1, b1, Wih, bih, bhh, W2, W5);
    k_sort<<<1, 1024>>>(u_items_mask);
    k_precompute<<<(NIP1 + 63) / 64, 256, PRE_SMEM>>>(item_emb, i_class, W3, b3);
    k_lstm<<<148, 256, LSTM_SMEM>>>(u_items, u_items_mask, Whh);
    k_user<<<B_ / 8, 256, USER_SMEM>>>(users, items, u_frids, u_frids_mask,
                                       u_frids_items, F_i, user_emb, item_emb,
                                       b2, W4, b4, b5, W6, b6, lambdas);
    k_cstat<<<2 * K_, 1024>>>();
    k_final<<<B_ / 256, 256>>>(alpha, (float*)d_out);
}

// round 13
// speedup vs baseline: 1.4583x; 1.0219x over previous
#include <cuda_runtime.h>
#include <math.h>

#define B_   4096
#define L_   50
#define K_   10
#define LI_  20
#define D_   64
#define C_   10
#define NIP1 50001

typedef unsigned long long ull;

// ---------------- scratch (static device globals; no allocation) -------------
__device__ float g_ju1[NIP1 * 256];   // gate-permuted x@Wih with all biases folded
__device__ float g_jv[NIP1 * D_];
__device__ float g_wc[74 * 256];      // (W1@Wih) gate-permuted
__device__ float g_bc[256];           // b1@Wih + bih + bhh, gate-permuted
__device__ float g_wi[192 * 128];     // interleaved (W2[k][c], W5[k][c])
__device__ float g_hu[B_ * D_];
__device__ float g_s1[K_ * B_];       // transposed [K][B]
__device__ float g_s2[K_ * B_];
__device__ float g_d1[K_ * B_];
__device__ float g_d2[K_ * B_];
__device__ float g_cs[4 * K_];
__device__ int   g_order[B_];

__device__ __forceinline__ float lrelu(float x) { return x >= 0.f ? x : 0.01f * x; }

// packed f32x2 fma (FFMA2) — only reachable via PTX
#define FMA2(d, a, b, c) \
    asm("fma.rn.f32x2 %0, %1, %2, %3;" : "=l"(d) : "l"(a), "l"(b), "l"(c))
#define PACK_DUP(d, x) \
    asm("mov.b64 %0, {%1, %1};" : "=l"(d) : "f"(x))
#define PACK2(d, lo, hi) \
    asm("mov.b64 %0, {%1, %2};" : "=l"(d) : "f"(lo), "f"(hi))
#define UNPACK2(lo, hi, p) \
    asm("mov.b64 {%0, %1}, %2;" : "=f"(lo), "=f"(hi) : "l"(p))

__device__ __forceinline__ float sigf(float x) {
    return __fdividef(1.f, 1.f + __expf(-x));
}
__device__ __forceinline__ float tanhf_fast(float x) {
    return 1.f - __fdividef(2.f, __expf(2.f * x) + 1.f);
}

// ============================================================================
// K0: combine Wc = W1@Wih (gate-permuted), bc; also build interleaved g_wi.
// ============================================================================
__global__ void k_combine(const float* __restrict__ W1, const float* __restrict__ b1,
                          const float* __restrict__ Wih, const float* __restrict__ bih,
                          const float* __restrict__ bhh,
                          const float* __restrict__ W2, const float* __restrict__ W5) {
    int k = blockIdx.x;
    int tid = threadIdx.x;
    if (k < 74) {
        int jp = tid;
        int c = jp >> 2, g = jp & 3;
        int j = c + 64 * g;
        float s = 0.f;
#pragma unroll
        for (int m = 0; m < 64; m++)
            s = fmaf(W1[k * 64 + m], __ldg(&Wih[m * 256 + j]), s);
        g_wc[k * 256 + jp] = s;
    } else if (k == 74) {
        int jp = tid;
        int c = jp >> 2, g = jp & 3;
        int j = c + 64 * g;
        float s = bih[j] + bhh[j];
#pragma unroll
        for (int m = 0; m < 64; m++)
            s = fmaf(b1[m], __ldg(&Wih[m * 256 + j]), s);
        g_bc[jp] = s;
    } else {
        int idx = (k - 75) * 256 + tid;    // 0 .. 192*128-1
        int kk = idx >> 7, j = idx & 127;
        int c = j >> 1;
        g_wi[idx] = (j & 1) ? W5[kk * 64 + c] : W2[kk * 64 + c];
    }
}

// ============================================================================
// K0b: counting sort of rows by u_items_mask, DESCENDING.
// ============================================================================
__global__ void k_sort(const int* __restrict__ mask) {
    __shared__ int cnt[64], off[64];
    int tid = threadIdx.x;
    if (tid < 64) cnt[tid] = 0;
    __syncthreads();
    for (int i = tid; i < B_; i += 1024) atomicAdd(&cnt[mask[i]], 1);
    __syncthreads();
    if (tid == 0) {
        int run = 0;
        for (int m = 50; m >= 1; m--) { off[m] = run; run += cnt[m]; }
    }
    __syncthreads();
    if (tid < 64) cnt[tid] = 0;
    __syncthreads();
    for (int i = tid; i < B_; i += 1024) {
        int m = mask[i];
        int pos = off[m] + atomicAdd(&cnt[m], 1);
        g_order[pos] = i;
    }
}

// ============================================================================
// K1: g_ju1 = x74 @ Wc + bc, g_jv = x74 @ W3 + b3. 64 rows/block (validated).
// ============================================================================
#define PRE_SMEM (64 * 76 * 4)

__global__ void __launch_bounds__(256)
k_precompute(const float* __restrict__ item_emb, const float* __restrict__ i_class,
             const float* __restrict__ W3, const float* __restrict__ b3) {
    extern __shared__ float sm[];
    float* xs = sm;                  // 64*76

    int tid = threadIdx.x;
    int c = tid & 31, rgrp = tid >> 5;
    int row0 = blockIdx.x * 64;
    for (int i = tid; i < 64 * 74; i += 256) {
        int rr = i / 74, k = i % 74;
        int row = row0 + rr;
        float v = 0.f;
        if (row < NIP1) v = (k < 64) ? item_emb[row * 64 + k] : i_class[row * 10 + (k - 64)];
        xs[rr * 76 + k] = v;
    }
    __syncthreads();

    ull a[8][4], jv[8];
    {
        const ull* bp = (const ull*)&g_bc[8 * c];
        ull b0 = __ldg(bp), b1v = __ldg(bp + 1), b2v = __ldg(bp + 2), b3v = __ldg(bp + 3);
        ull jb = __ldg((const ull*)&b3[2 * c]);
#pragma unroll
        for (int r = 0; r < 8; r++) {
            a[r][0] = b0; a[r][1] = b1v; a[r][2] = b2v; a[r][3] = b3v;
            jv[r] = jb;
        }
    }
#pragma unroll 2
    for (int k = 0; k < 74; k++) {
        const ulonglong2* wp = (const ulonglong2*)&g_wc[k * 256 + 8 * c];
        ulonglong2 wa = __ldg(wp), wb = __ldg(wp + 1);
        ull w3v = __ldg((const ull*)&W3[k * 64 + 2 * c]);
        const float* xr = &xs[(rgrp * 8) * 76 + k];
#pragma unroll
        for (int r = 0; r < 8; r++) {
            float av = xr[r * 76];
            ull ad; PACK_DUP(ad, av);
            FMA2(a[r][0], ad, wa.x, a[r][0]);
            FMA2(a[r][1], ad, wa.y, a[r][1]);
            FMA2(a[r][2], ad, wb.x, a[r][2]);
            FMA2(a[r][3], ad, wb.y, a[r][3]);
            FMA2(jv[r], ad, w3v, jv[r]);
        }
    }
#pragma unroll
    for (int r = 0; r < 8; r++) {
        int row = row0 + rgrp * 8 + r;
        if (row < NIP1) {
            ull* o = (ull*)&g_ju1[row * 256 + 8 * c];
            o[0] = a[r][0]; o[1] = a[r][1]; o[2] = a[r][2]; o[3] = a[r][3];
            *(ull*)&g_jv[row * 64 + 2 * c] = jv[r];
        }
    }
}

// ============================================================================
// K2: PAIR-SPLIT LSTM. Each 4-row chunk is computed by a PAIR of warps
// (2p, 2p+1) living on DIFFERENT SMSPs; each warp owns 32 cells (half=wid&1,
// cell = 32*half + lane). h is exchanged through pair-shared smem, one named
// barrier (64 threads) per step. Per-warp per-step: 512 FFMA2 = 1024 fma-cyc
// (half the 4-row single-warp floor). LPT: pair p takes chunk p and chunk
// 1183-p (if <=1023). Accumulation pairing (r0,r1)/(r2,r3) per gate is
// unchanged -> bitwise-identical results.
// ============================================================================
#define LSTM_PFL (512 + 200 + 8)   // per-pair floats: hbuf x2 (2x256) + idxs + pad
#define LSTM_SMEM ((64*256 + 4*LSTM_PFL) * 4)

__global__ void __launch_bounds__(256, 1)
k_lstm(const int* __restrict__ u_items, const int* __restrict__ u_items_mask,
       const float* __restrict__ Whh) {
    extern __shared__ float sm[];
    float* Wp = sm;                               // 64*256 gate-permuted Whh
    int tid = threadIdx.x;
    int wid = tid >> 5, lane = tid & 31;
    int pid = wid >> 1;                           // pair 0..3
    int half = wid & 1;                           // cell half
    float* hbuf = Wp + 64 * 256 + pid * LSTM_PFL; // 2 x 256 (layout [cell][row])
    int*   idxs = (int*)(hbuf + 512);             // 4*50

    // stage gate-permuted Whh: Wp[k][cell*4+g] = Whh[k][cell + 64*g]
    for (int i = tid; i < 64 * 256; i += 256) {
        int k = i >> 8, jp = i & 255;
        Wp[i] = Whh[k * 256 + (jp >> 2) + 64 * (jp & 3)];
    }
    __syncthreads();   // the only block-wide barrier

    int cell = half * 32 + lane;
    int p = pid * 148 + blockIdx.x;               // pair id 0..591
    const float* WpL = Wp + cell * 4;

#pragma unroll 1
    for (int ci = 0; ci < 2; ci++) {
        int chunk = ci ? (1183 - p) : p;          // ci=0: 0..591, ci=1: 592..1183
        if (chunk > 1023) continue;               // both pair warps agree

        int rows[4], msk[4];
#pragma unroll
        for (int r = 0; r < 4; r++) {
            rows[r] = g_order[chunk * 4 + r];
            msk[r] = u_items_mask[rows[r]];
        }
        int maxm = msk[0];                        // sorted desc -> first is max

        // stage idxs (each warp handles its 2 rows) and zero its hbuf half
        for (int i = lane; i < 100; i += 32) {
            int r = 2 * half + i / 50, t = i % 50;
            idxs[r * 50 + t] = u_items[rows[r] * 50 + t];
        }
        {
            float4 z4; z4.x = 0.f; z4.y = 0.f; z4.z = 0.f; z4.w = 0.f;
            *(float4*)&hbuf[cell * 4] = z4;       // buf0[cell][0..3] = 0
        }
        asm volatile("bar.sync %0, 64;" :: "r"(pid + 1) : "memory");

        float c_reg[4];
#pragma unroll
        for (int r = 0; r < 4; r++) c_reg[r] = 0.f;

        // prefetch x-part for t=0: this cell's 4 gates, per row
        float4 p4[4];
#pragma unroll
        for (int r = 0; r < 4; r++)
            p4[r] = *(const float4*)&g_ju1[idxs[r * 50] * 256 + cell * 4];

        for (int t = 0; t < maxm; t++) {
            const float* hr = hbuf + (t & 1) * 256;
            float* hw = hbuf + ((t + 1) & 1) * 256;

            // acc[gate][rowpair], init from x-part (biases folded)
            ull acc[4][2];
            PACK2(acc[0][0], p4[0].x, p4[1].x); PACK2(acc[0][1], p4[2].x, p4[3].x);
            PACK2(acc[1][0], p4[0].y, p4[1].y); PACK2(acc[1][1], p4[2].y, p4[3].y);
            PACK2(acc[2][0], p4[0].z, p4[1].z); PACK2(acc[2][1], p4[2].z, p4[3].z);
            PACK2(acc[3][0], p4[0].w, p4[1].w); PACK2(acc[3][1], p4[2].w, p4[3].w);

            if (t + 1 < maxm) {
#pragma unroll
                for (int r = 0; r < 4; r++)
                    p4[r] = *(const float4*)&g_ju1[idxs[r * 50 + t + 1] * 256 + cell * 4];
            }

            // h @ Whh over 64 dims, software-pipelined
            float4 nw = *(const float4*)&WpL[0];
            float4 nh = *(const float4*)&hr[0];
#pragma unroll 8
            for (int k = 0; k < 64; k++) {
                float4 w = nw;
                float4 h = nh;
                int kn = (k + 1) & 63;
                nw = *(const float4*)&WpL[kn * 256];
                nh = *(const float4*)&hr[kn * 4];
                ull h01, h23, d;
                PACK2(h01, h.x, h.y);
                PACK2(h23, h.z, h.w);
                PACK_DUP(d, w.x); FMA2(acc[0][0], h01, d, acc[0][0]); FMA2(acc[0][1], h23, d, acc[0][1]);
                PACK_DUP(d, w.y); FMA2(acc[1][0], h01, d, acc[1][0]); FMA2(acc[1][1], h23, d, acc[1][1]);
                PACK_DUP(d, w.z); FMA2(acc[2][0], h01, d, acc[2][0]); FMA2(acc[2][1], h23, d, acc[2][1]);
                PACK_DUP(d, w.w); FMA2(acc[3][0], h01, d, acc[3][0]); FMA2(acc[3][1], h23, d, acc[3][1]);
            }

            // epilogue: 4 (row, this-cell) updates per lane
            float hval[4];
#pragma unroll
            for (int rp = 0; rp < 2; rp++) {
                float gi0, gi1, gf0, gf1, gg0, gg1, go0, go1;
                UNPACK2(gi0, gi1, acc[0][rp]);
                UNPACK2(gf0, gf1, acc[1][rp]);
                UNPACK2(gg0, gg1, acc[2][rp]);
                UNPACK2(go0, go1, acc[3][rp]);
#pragma unroll
                for (int h2 = 0; h2 < 2; h2++) {
                    int r = 2 * rp + h2;
                    float gi = h2 ? gi1 : gi0;
                    float gf = h2 ? gf1 : gf0;
                    float gg = h2 ? gg1 : gg0;
                    float go = h2 ? go1 : go0;
                    float cc = sigf(gf) * c_reg[r] + sigf(gi) * tanhf_fast(gg);
                    c_reg[r] = cc;
                    hval[r] = sigf(go) * tanhf_fast(cc);
                }
            }
            float4 hv4;
            hv4.x = hval[0]; hv4.y = hval[1]; hv4.z = hval[2]; hv4.w = hval[3];
            *(float4*)&hw[cell * 4] = hv4;

#pragma unroll
            for (int r = 0; r < 4; r++) {
                if (t == msk[r] - 1)
                    g_hu[rows[r] * 64 + cell] = hval[r];
            }
            // pair barrier: both halves' h visible before next step's GEMM
            asm volatile("bar.sync %0, 64;" :: "r"(pid + 1) : "memory");
        }
    }
}

// ============================================================================
// K3: merged per-row user stage (validated).
// ============================================================================
#define USER_SMEM ((128 + 128 + 8*384) * 4)

__global__ void __launch_bounds__(256)
k_user(const int* __restrict__ users, const int* __restrict__ items,
       const int* __restrict__ u_frids, const int* __restrict__ u_frids_mask,
       const int* __restrict__ u_frids_items, const int* __restrict__ F_i,
       const float* __restrict__ user_emb, const float* __restrict__ item_emb,
       const float* __restrict__ b2,
       const float* __restrict__ W4, const float* __restrict__ b4,
       const float* __restrict__ b5,
       const float* __restrict__ W6, const float* __restrict__ b6,
       const float* __restrict__ lambdas) {
    extern __shared__ float sm[];
    float* W4s = sm;                 // 128
    float* W6s = W4s + 128;          // 128
    float* zz  = W6s + 128;          // 8 * 384

    int tid = threadIdx.x;
    if (tid < 128) W4s[tid] = W4[tid];
    else W6s[tid - 128] = W6[tid - 128];
    __syncthreads();

    int w = tid >> 5, lane = tid & 31;
    int row = blockIdx.x * 8 + w;
    int c0 = lane * 2;
    float l0 = lambdas[0], l1 = lambdas[1], l2 = lambdas[2], l3 = lambdas[3];
    float b4v = b4[0], b6v = b6[0];

    int usr = users[row], itm = items[row];
    float2 u2  = *(const float2*)(user_emb + usr * 64 + c0);
    float2 ie2 = *(const float2*)(item_emb + itm * 64 + c0);
    float2 hu2 = *(const float2*)(g_hu + row * 64 + c0);

    float px[K_], py[K_];
#pragma unroll
    for (int k = 0; k < K_; k++) { px[k] = 0.f; py[k] = 0.f; }
    const int* ip = u_frids_items + row * (K_ * LI_);
#pragma unroll
    for (int k = 0; k < K_; k++) {
#pragma unroll
        for (int li = 0; li < LI_; li++) {
            int idx = ip[k * LI_ + li];
            float2 j2 = *(const float2*)(g_jv + idx * 64 + c0);
            px[k] += j2.x; py[k] += j2.y;
        }
    }

    float du_p = u2.x * W4s[c0] + u2.y * W4s[c0 + 1];
    float at_p[K_];
#pragma unroll
    for (int k = 0; k < K_; k++) {
        int fid = u_frids[row * K_ + k];
        float2 v2 = *(const float2*)(user_emb + fid * 64 + c0);
        at_p[k] = v2.x * W4s[64 + c0] + v2.y * W4s[65 + c0];
    }
#pragma unroll
    for (int o = 16; o; o >>= 1) {
        du_p += __shfl_xor_sync(0xffffffffu, du_p, o);
#pragma unroll
        for (int k = 0; k < K_; k++) at_p[k] += __shfl_xor_sync(0xffffffffu, at_p[k], o);
    }
    int fm = u_frids_mask[row];
    float at[K_];
#pragma unroll
    for (int k = 0; k < K_; k++) at[k] = lrelu(du_p + at_p[k] + b4v);
    float mx = -1e30f;
#pragma unroll
    for (int k = 0; k < K_; k++) if (k < fm) mx = fmaxf(mx, at[k]);
    float se = 0.f, ev[K_];
#pragma unroll
    for (int k = 0; k < K_; k++) { ev[k] = (k < fm) ? __expf(at[k] - mx) : 0.f; se += ev[k]; }
    float inv = __fdividef(1.f, se * (float)fm);

    float sux = 0.f, suy = 0.f;
#pragma unroll
    for (int k = 0; k < K_; k++) {
        float wk = ev[k] * inv;
        sux = fmaf(wk, px[k], sux);
        suy = fmaf(wk, py[k], suy);
    }

    ull* z = (ull*)(zz + w * 384);
    PACK2(z[c0],       hu2.x, sux);
    PACK2(z[c0 + 1],   hu2.y, suy);
    PACK2(z[64 + c0],     ie2.x, ie2.x);
    PACK2(z[64 + c0 + 1], ie2.y, ie2.y);
    PACK2(z[128 + c0],     hu2.x * ie2.x, sux * ie2.x);
    PACK2(z[128 + c0 + 1], hu2.y * ie2.y, suy * ie2.y);
    __syncwarp();
    ull acc0, acc1;
    PACK2(acc0, b2[c0], b5[c0]);
    PACK2(acc1, b2[c0 + 1], b5[c0 + 1]);
    const ulonglong2* wip = (const ulonglong2*)&g_wi[4 * lane];
#pragma unroll 8
    for (int k = 0; k < 192; k++) {
        ull zk = z[k];
        ulonglong2 wv = __ldg(wip + k * 32);
        FMA2(acc0, zk, wv.x, acc0);
        FMA2(acc1, zk, wv.y, acc1);
    }
    float huix, suix, huiy, suiy;
    UNPACK2(huix, suix, acc0);
    UNPACK2(huiy, suiy, acc1);

    float zsx = l0 * hu2.x + l1 * huix + l2 * sux + l3 * suix;
    float zsy = l0 * hu2.y + l1 * huiy + l2 * suy + l3 * suiy;

    float di_p = ie2.x * W6s[c0] + ie2.y * W6s[c0 + 1];
#pragma unroll
    for (int o = 16; o; o >>= 1) di_p += __shfl_xor_sync(0xffffffffu, di_p, o);

#pragma unroll
    for (int s = 0; s < 2; s++) {
        float sp[K_], dp[K_];
#pragma unroll
        for (int k = 0; k < K_; k++) {
            int fi = F_i[(row * 2 + s) * K_ + k];
            float2 f2 = *(const float2*)(item_emb + fi * 64 + c0);
            sp[k] = f2.x * W6s[64 + c0] + f2.y * W6s[65 + c0];
            dp[k] = f2.x * zsx + f2.y * zsy;
        }
#pragma unroll
        for (int o = 16; o; o >>= 1) {
#pragma unroll
            for (int k = 0; k < K_; k++) {
                sp[k] += __shfl_xor_sync(0xffffffffu, sp[k], o);
                dp[k] += __shfl_xor_sync(0xffffffffu, dp[k], o);
            }
        }
        if (lane == 0) {
            float* spo = s ? g_s2 : g_s1;
            float* dpo = s ? g_d2 : g_d1;
#pragma unroll
            for (int k = 0; k < K_; k++) {
                spo[k * B_ + row] = lrelu(di_p + sp[k] + b6v);
                dpo[k * B_ + row] = dp[k];
            }
        }
    }
}

// ============================================================================
// K4: per-column softmax stats (online), coalesced [K][B].
// ============================================================================
__global__ void k_cstat() {
    int sel = blockIdx.x / K_;
    int k = blockIdx.x % K_;
    const float* s = (sel ? g_s2 : g_s1) + k * B_;
    __shared__ float rm[1024], rs[1024];
    int tid = threadIdx.x;
    float m = -1e30f, acc = 0.f;
    for (int i = tid; i < B_; i += 1024) {
        float x = s[i];
        float nm = fmaxf(m, x);
        acc = acc * __expf(m - nm) + __expf(x - nm);
        m = nm;
    }
    rm[tid] = m; rs[tid] = acc;
    __syncthreads();
    for (int o = 512; o; o >>= 1) {
        if (tid < o) {
            float m2 = rm[tid + o], s2v = rs[tid + o];
            float nm = fmaxf(rm[tid], m2);
            rs[tid] = rs[tid] * __expf(rm[tid] - nm) + s2v * __expf(m2 - nm);
            rm[tid] = nm;
        }
        __syncthreads();
    }
    if (tid == 0) { g_cs[sel * 2 * K_ + k] = rm[0]; g_cs[sel * 2 * K_ + K_ + k] = rs[0]; }
}

// ============================================================================
// K5: final S + sigmoid (coalesced [K][B] reads)
// ============================================================================
__global__ void k_final(const float* __restrict__ alpha, float* __restrict__ out) {
    int b = blockIdx.x * 256 + threadIdx.x;
    float a = alpha[0];
    float S1 = 0.f, S2 = 0.f;
#pragma unroll
    for (int k = 0; k < K_; k++) {
        S1 += __expf(g_s1[k * B_ + b] - g_cs[k]) / g_cs[K_ + k] * g_d1[k * B_ + b];
        S2 += __expf(g_s2[k * B_ + b] - g_cs[2 * K_ + k]) / g_cs[3 * K_ + k] * g_d2[k * B_ + b];
    }
    float S = a * S1 + (1.f - a) * S2;
    out[b] = __fdividef(1.f, 1.f + __expf(-S));
}

// ============================================================================
extern "C" void kernel_launch(void* const* d_in, const int* in_sizes, int n_in,
                              void* d_out, int out_size) {
    const int*   users        = (const int*)d_in[0];
    const int*   items        = (const int*)d_in[1];
    const int*   u_items      = (const int*)d_in[2];
    const int*   u_items_mask = (const int*)d_in[3];
    const int*   u_frids      = (const int*)d_in[4];
    const int*   u_frids_mask = (const int*)d_in[5];
    const int*   u_frids_items= (const int*)d_in[6];
    const int*   F_i          = (const int*)d_in[7];
    const float* user_emb     = (const float*)d_in[8];
    const float* item_emb     = (const float*)d_in[9];
    const float* i_class      = (const float*)d_in[10];
    const float* W1  = (const float*)d_in[11];
    const float* b1  = (const float*)d_in[12];
    const float* Wih = (const float*)d_in[13];
    const float* Whh = (const float*)d_in[14];
    const float* bih = (const float*)d_in[15];
    const float* bhh = (const float*)d_in[16];
    const float* W2  = (const float*)d_in[17];
    const float* b2  = (const float*)d_in[18];
    const float* W3  = (const float*)d_in[19];
    const float* b3  = (const float*)d_in[20];
    const float* W4  = (const float*)d_in[21];
    const float* b4  = (const float*)d_in[22];
    const float* W5  = (const float*)d_in[23];
    const float* b5  = (const float*)d_in[24];
    const float* W6  = (const float*)d_in[25];
    const float* b6  = (const float*)d_in[26];
    const float* alpha   = (const float*)d_in[27];
    const float* lambdas = (const float*)d_in[28];

    cudaFuncSetAttribute(k_precompute, cudaFuncAttributeMaxDynamicSharedMemorySize, PRE_SMEM);
    cudaFuncSetAttribute(k_lstm, cudaFuncAttributeMaxDynamicSharedMemorySize, LSTM_SMEM);
    cudaFuncSetAttribute(k_user, cudaFuncAttributeMaxDynamicSharedMemorySize, USER_SMEM);

    k_combine<<<171, 256>>>(W1, b1, Wih, bih, bhh, W2, W5);
    k_sort<<<1, 1024>>>(u_items_mask);
    k_precompute<<<(NIP1 + 63) / 64, 256, PRE_SMEM>>>(item_emb, i_class, W3, b3);
    k_lstm<<<148, 256, LSTM_SMEM>>>(u_items, u_items_mask, Whh);
    k_user<<<B_ / 8, 256, USER_SMEM>>>(users, items, u_frids, u_frids_mask,
                                       u_frids_items, F_i, user_emb, item_emb,
                                       b2, W4, b4, b5, W6, b6, lambdas);
    k_cstat<<<2 * K_, 1024>>>();
    k_final<<<B_ / 256, 256>>>(alpha, (float*)d_out);
}

// round 14
// speedup vs baseline: 1.4687x; 1.0071x over previous
#include <cuda_runtime.h>
#include <math.h>

#define B_   4096
#define L_   50
#define K_   10
#define LI_  20
#define D_   64
#define C_   10
#define NIP1 50001

typedef unsigned long long ull;

// ---------------- scratch (static device globals; no allocation) -------------
__device__ float g_ju1[NIP1 * 256];   // gate-permuted x@Wih with all biases folded
__device__ float g_jv[NIP1 * D_];
__device__ float g_wc[74 * 256];      // (W1@Wih) gate-permuted
__device__ float g_bc[256];           // b1@Wih + bih + bhh, gate-permuted
__device__ float g_wi[192 * 128];     // interleaved (W2[k][c], W5[k][c])
__device__ float g_hu[B_ * D_];
__device__ float g_s1[K_ * B_];       // transposed [K][B]
__device__ float g_s2[K_ * B_];
__device__ float g_d1[K_ * B_];
__device__ float g_d2[K_ * B_];
__device__ float g_cs[4 * K_];
__device__ int   g_order[B_];

__device__ __forceinline__ float lrelu(float x) { return x >= 0.f ? x : 0.01f * x; }

// packed f32x2 fma (FFMA2) — only reachable via PTX
#define FMA2(d, a, b, c) \
    asm("fma.rn.f32x2 %0, %1, %2, %3;" : "=l"(d) : "l"(a), "l"(b), "l"(c))
#define PACK_DUP(d, x) \
    asm("mov.b64 %0, {%1, %1};" : "=l"(d) : "f"(x))
#define PACK2(d, lo, hi) \
    asm("mov.b64 %0, {%1, %2};" : "=l"(d) : "f"(lo), "f"(hi))
#define UNPACK2(lo, hi, p) \
    asm("mov.b64 {%0, %1}, %2;" : "=f"(lo), "=f"(hi) : "l"(p))

__device__ __forceinline__ float sigf(float x) {
    return __fdividef(1.f, 1.f + __expf(-x));
}
__device__ __forceinline__ float tanhf_fast(float x) {
    return 1.f - __fdividef(2.f, __expf(2.f * x) + 1.f);
}

// ============================================================================
// K0: combine Wc = W1@Wih (gate-permuted), bc; also build interleaved g_wi.
// ============================================================================
__global__ void k_combine(const float* __restrict__ W1, const float* __restrict__ b1,
                          const float* __restrict__ Wih, const float* __restrict__ bih,
                          const float* __restrict__ bhh,
                          const float* __restrict__ W2, const float* __restrict__ W5) {
    int k = blockIdx.x;
    int tid = threadIdx.x;
    if (k < 74) {
        int jp = tid;
        int c = jp >> 2, g = jp & 3;
        int j = c + 64 * g;
        float s = 0.f;
#pragma unroll
        for (int m = 0; m < 64; m++)
            s = fmaf(W1[k * 64 + m], __ldg(&Wih[m * 256 + j]), s);
        g_wc[k * 256 + jp] = s;
    } else if (k == 74) {
        int jp = tid;
        int c = jp >> 2, g = jp & 3;
        int j = c + 64 * g;
        float s = bih[j] + bhh[j];
#pragma unroll
        for (int m = 0; m < 64; m++)
            s = fmaf(b1[m], __ldg(&Wih[m * 256 + j]), s);
        g_bc[jp] = s;
    } else {
        int idx = (k - 75) * 256 + tid;    // 0 .. 192*128-1
        int kk = idx >> 7, j = idx & 127;
        int c = j >> 1;
        g_wi[idx] = (j & 1) ? W5[kk * 64 + c] : W2[kk * 64 + c];
    }
}

// ============================================================================
// K0b: counting sort of rows by u_items_mask, DESCENDING.
// ============================================================================
__global__ void k_sort(const int* __restrict__ mask) {
    __shared__ int cnt[64], off[64];
    int tid = threadIdx.x;
    if (tid < 64) cnt[tid] = 0;
    __syncthreads();
    for (int i = tid; i < B_; i += 1024) atomicAdd(&cnt[mask[i]], 1);
    __syncthreads();
    if (tid == 0) {
        int run = 0;
        for (int m = 50; m >= 1; m--) { off[m] = run; run += cnt[m]; }
    }
    __syncthreads();
    if (tid < 64) cnt[tid] = 0;
    __syncthreads();
    for (int i = tid; i < B_; i += 1024) {
        int m = mask[i];
        int pos = off[m] + atomicAdd(&cnt[m], 1);
        g_order[pos] = i;
    }
}

// ============================================================================
// K1: g_ju1 = x74 @ Wc + bc, g_jv = x74 @ W3 + b3. 64 rows/block (validated).
// ============================================================================
#define PRE_SMEM (64 * 76 * 4)

__global__ void __launch_bounds__(256)
k_precompute(const float* __restrict__ item_emb, const float* __restrict__ i_class,
             const float* __restrict__ W3, const float* __restrict__ b3) {
    extern __shared__ float sm[];
    float* xs = sm;                  // 64*76

    int tid = threadIdx.x;
    int c = tid & 31, rgrp = tid >> 5;
    int row0 = blockIdx.x * 64;
    for (int i = tid; i < 64 * 74; i += 256) {
        int rr = i / 74, k = i % 74;
        int row = row0 + rr;
        float v = 0.f;
        if (row < NIP1) v = (k < 64) ? item_emb[row * 64 + k] : i_class[row * 10 + (k - 64)];
        xs[rr * 76 + k] = v;
    }
    __syncthreads();

    ull a[8][4], jv[8];
    {
        const ull* bp = (const ull*)&g_bc[8 * c];
        ull b0 = __ldg(bp), b1v = __ldg(bp + 1), b2v = __ldg(bp + 2), b3v = __ldg(bp + 3);
        ull jb = __ldg((const ull*)&b3[2 * c]);
#pragma unroll
        for (int r = 0; r < 8; r++) {
            a[r][0] = b0; a[r][1] = b1v; a[r][2] = b2v; a[r][3] = b3v;
            jv[r] = jb;
        }
    }
#pragma unroll 2
    for (int k = 0; k < 74; k++) {
        const ulonglong2* wp = (const ulonglong2*)&g_wc[k * 256 + 8 * c];
        ulonglong2 wa = __ldg(wp), wb = __ldg(wp + 1);
        ull w3v = __ldg((const ull*)&W3[k * 64 + 2 * c]);
        const float* xr = &xs[(rgrp * 8) * 76 + k];
#pragma unroll
        for (int r = 0; r < 8; r++) {
            float av = xr[r * 76];
            ull ad; PACK_DUP(ad, av);
            FMA2(a[r][0], ad, wa.x, a[r][0]);
            FMA2(a[r][1], ad, wa.y, a[r][1]);
            FMA2(a[r][2], ad, wb.x, a[r][2]);
            FMA2(a[r][3], ad, wb.y, a[r][3]);
            FMA2(jv[r], ad, w3v, jv[r]);
        }
    }
#pragma unroll
    for (int r = 0; r < 8; r++) {
        int row = row0 + rgrp * 8 + r;
        if (row < NIP1) {
            ull* o = (ull*)&g_ju1[row * 256 + 8 * c];
            o[0] = a[r][0]; o[1] = a[r][1]; o[2] = a[r][2]; o[3] = a[r][3];
            *(ull*)&g_jv[row * 64 + 2 * c] = jv[r];
        }
    }
}

// ============================================================================
// K2: PAIR-SPLIT LSTM (round-13 validated, 108us).
// ============================================================================
#define LSTM_PFL (512 + 200 + 8)   // per-pair floats: hbuf x2 (2x256) + idxs + pad
#define LSTM_SMEM ((64*256 + 4*LSTM_PFL) * 4)

__global__ void __launch_bounds__(256, 1)
k_lstm(const int* __restrict__ u_items, const int* __restrict__ u_items_mask,
       const float* __restrict__ Whh) {
    extern __shared__ float sm[];
    float* Wp = sm;                               // 64*256 gate-permuted Whh
    int tid = threadIdx.x;
    int wid = tid >> 5, lane = tid & 31;
    int pid = wid >> 1;                           // pair 0..3
    int half = wid & 1;                           // cell half
    float* hbuf = Wp + 64 * 256 + pid * LSTM_PFL; // 2 x 256 (layout [cell][row])
    int*   idxs = (int*)(hbuf + 512);             // 4*50

    for (int i = tid; i < 64 * 256; i += 256) {
        int k = i >> 8, jp = i & 255;
        Wp[i] = Whh[k * 256 + (jp >> 2) + 64 * (jp & 3)];
    }
    __syncthreads();   // the only block-wide barrier

    int cell = half * 32 + lane;
    int p = pid * 148 + blockIdx.x;               // pair id 0..591
    const float* WpL = Wp + cell * 4;

#pragma unroll 1
    for (int ci = 0; ci < 2; ci++) {
        int chunk = ci ? (1183 - p) : p;
        if (chunk > 1023) continue;

        int rows[4], msk[4];
#pragma unroll
        for (int r = 0; r < 4; r++) {
            rows[r] = g_order[chunk * 4 + r];
            msk[r] = u_items_mask[rows[r]];
        }
        int maxm = msk[0];

        for (int i = lane; i < 100; i += 32) {
            int r = 2 * half + i / 50, t = i % 50;
            idxs[r * 50 + t] = u_items[rows[r] * 50 + t];
        }
        {
            float4 z4; z4.x = 0.f; z4.y = 0.f; z4.z = 0.f; z4.w = 0.f;
            *(float4*)&hbuf[cell * 4] = z4;
        }
        asm volatile("bar.sync %0, 64;" :: "r"(pid + 1) : "memory");

        float c_reg[4];
#pragma unroll
        for (int r = 0; r < 4; r++) c_reg[r] = 0.f;

        float4 p4[4];
#pragma unroll
        for (int r = 0; r < 4; r++)
            p4[r] = *(const float4*)&g_ju1[idxs[r * 50] * 256 + cell * 4];

        for (int t = 0; t < maxm; t++) {
            const float* hr = hbuf + (t & 1) * 256;
            float* hw = hbuf + ((t + 1) & 1) * 256;

            ull acc[4][2];
            PACK2(acc[0][0], p4[0].x, p4[1].x); PACK2(acc[0][1], p4[2].x, p4[3].x);
            PACK2(acc[1][0], p4[0].y, p4[1].y); PACK2(acc[1][1], p4[2].y, p4[3].y);
            PACK2(acc[2][0], p4[0].z, p4[1].z); PACK2(acc[2][1], p4[2].z, p4[3].z);
            PACK2(acc[3][0], p4[0].w, p4[1].w); PACK2(acc[3][1], p4[2].w, p4[3].w);

            if (t + 1 < maxm) {
#pragma unroll
                for (int r = 0; r < 4; r++)
                    p4[r] = *(const float4*)&g_ju1[idxs[r * 50 + t + 1] * 256 + cell * 4];
            }

            float4 nw = *(const float4*)&WpL[0];
            float4 nh = *(const float4*)&hr[0];
#pragma unroll 8
            for (int k = 0; k < 64; k++) {
                float4 w = nw;
                float4 h = nh;
                int kn = (k + 1) & 63;
                nw = *(const float4*)&WpL[kn * 256];
                nh = *(const float4*)&hr[kn * 4];
                ull h01, h23, d;
                PACK2(h01, h.x, h.y);
                PACK2(h23, h.z, h.w);
                PACK_DUP(d, w.x); FMA2(acc[0][0], h01, d, acc[0][0]); FMA2(acc[0][1], h23, d, acc[0][1]);
                PACK_DUP(d, w.y); FMA2(acc[1][0], h01, d, acc[1][0]); FMA2(acc[1][1], h23, d, acc[1][1]);
                PACK_DUP(d, w.z); FMA2(acc[2][0], h01, d, acc[2][0]); FMA2(acc[2][1], h23, d, acc[2][1]);
                PACK_DUP(d, w.w); FMA2(acc[3][0], h01, d, acc[3][0]); FMA2(acc[3][1], h23, d, acc[3][1]);
            }

            float hval[4];
#pragma unroll
            for (int rp = 0; rp < 2; rp++) {
                float gi0, gi1, gf0, gf1, gg0, gg1, go0, go1;
                UNPACK2(gi0, gi1, acc[0][rp]);
                UNPACK2(gf0, gf1, acc[1][rp]);
                UNPACK2(gg0, gg1, acc[2][rp]);
                UNPACK2(go0, go1, acc[3][rp]);
#pragma unroll
                for (int h2 = 0; h2 < 2; h2++) {
                    int r = 2 * rp + h2;
                    float gi = h2 ? gi1 : gi0;
                    float gf = h2 ? gf1 : gf0;
                    float gg = h2 ? gg1 : gg0;
                    float go = h2 ? go1 : go0;
                    float cc = sigf(gf) * c_reg[r] + sigf(gi) * tanhf_fast(gg);
                    c_reg[r] = cc;
                    hval[r] = sigf(go) * tanhf_fast(cc);
                }
            }
            float4 hv4;
            hv4.x = hval[0]; hv4.y = hval[1]; hv4.z = hval[2]; hv4.w = hval[3];
            *(float4*)&hw[cell * 4] = hv4;

#pragma unroll
            for (int r = 0; r < 4; r++) {
                if (t == msk[r] - 1)
                    g_hu[rows[r] * 64 + cell] = hval[r];
            }
            asm volatile("bar.sync %0, 64;" :: "r"(pid + 1) : "memory");
        }
    }
}

// ============================================================================
// K3: PAIR-SPLIT user stage. 512 threads = 8 rows x 2 warps. Per row:
//   warp0: friends 0-4 gather + at partials + du;  GEMV k 0-95;   F_i s=0
//   warp1: friends 5-9 gather + at partials + di;  GEMV k 96-191; F_i s=1
// Exchanges via per-row smem + named pair barrier. All reductions stay
// intra-warp (same shuffle order); only split-sum order differs (~ulps).
// ============================================================================
#define USER_ROWF 784   // floats per row region: ex16 + sux128 + zz384 + accx256
#define USER_SMEM ((256 + 8 * USER_ROWF) * 4)

__global__ void __launch_bounds__(512)
k_user(const int* __restrict__ users, const int* __restrict__ items,
       const int* __restrict__ u_frids, const int* __restrict__ u_frids_mask,
       const int* __restrict__ u_frids_items, const int* __restrict__ F_i,
       const float* __restrict__ user_emb, const float* __restrict__ item_emb,
       const float* __restrict__ b2,
       const float* __restrict__ W4, const float* __restrict__ b4,
       const float* __restrict__ b5,
       const float* __restrict__ W6, const float* __restrict__ b6,
       const float* __restrict__ lambdas) {
    extern __shared__ float sm[];
    float* W4s = sm;                  // 128
    float* W6s = W4s + 128;           // 128
    float* rowbuf = W6s + 128;        // 8 * USER_ROWF

    int tid = threadIdx.x;
    if (tid < 128) W4s[tid] = W4[tid];
    else if (tid < 256) W6s[tid - 128] = W6[tid - 128];
    __syncthreads();

    int rp = tid >> 6;                // row slot 0..7
    int w2 = (tid >> 5) & 1;          // pair half
    int lane = tid & 31;
    int row = blockIdx.x * 8 + rp;
    int c0 = lane * 2;
    int barid = rp + 1;
    float* rb  = rowbuf + rp * USER_ROWF;
    float* ex  = rb;                  // 16: [w*8+0..4]=at partials, [w*8+5]=du/di
    float* sux = rb + 16;             // 128: su partials [w*64 + c]
    ull*  zz   = (ull*)(rb + 144);    // 192 ull
    ull*  accx = (ull*)(rb + 528);    // 128 ull: [w*64 + lane*2 + {0,1}]

    float l0 = lambdas[0], l1 = lambdas[1], l2 = lambdas[2], l3 = lambdas[3];
    float b4v = b4[0], b6v = b6[0];

    int usr = users[row], itm = items[row];
    float2 ie2 = *(const float2*)(item_emb + itm * 64 + c0);
    float2 hu2 = *(const float2*)(g_hu + row * 64 + c0);

    // ---- gather own 5 friends' jv sums ----
    int kbase = w2 * 5;
    float px[5], py[5];
#pragma unroll
    for (int k5 = 0; k5 < 5; k5++) { px[k5] = 0.f; py[k5] = 0.f; }
    const int* ip = u_frids_items + (row * K_ + kbase) * LI_;
#pragma unroll
    for (int k5 = 0; k5 < 5; k5++) {
#pragma unroll
        for (int li = 0; li < LI_; li++) {
            int idx = ip[k5 * LI_ + li];
            float2 j2 = *(const float2*)(g_jv + idx * 64 + c0);
            px[k5] += j2.x; py[k5] += j2.y;
        }
    }

    // ---- at partials (own 5 friends) + du (w0) / di (w1), intra-warp ----
    float v0;
    if (w2 == 0) {
        float2 u2 = *(const float2*)(user_emb + usr * 64 + c0);
        v0 = u2.x * W4s[c0] + u2.y * W4s[c0 + 1];
    } else {
        v0 = ie2.x * W6s[c0] + ie2.y * W6s[c0 + 1];
    }
    float at_p[5];
#pragma unroll
    for (int k5 = 0; k5 < 5; k5++) {
        int fid = u_frids[row * K_ + kbase + k5];
        float2 vv = *(const float2*)(user_emb + fid * 64 + c0);
        at_p[k5] = vv.x * W4s[64 + c0] + vv.y * W4s[65 + c0];
    }
#pragma unroll
    for (int o = 16; o; o >>= 1) {
        v0 += __shfl_xor_sync(0xffffffffu, v0, o);
#pragma unroll
        for (int k5 = 0; k5 < 5; k5++)
            at_p[k5] += __shfl_xor_sync(0xffffffffu, at_p[k5], o);
    }
    if (lane == 0) {
#pragma unroll
        for (int k5 = 0; k5 < 5; k5++) ex[w2 * 8 + k5] = at_p[k5];
        ex[w2 * 8 + 5] = v0;
    }
    asm volatile("bar.sync %0, 64;" :: "r"(barid) : "memory");

    float du = ex[5];
    float di = ex[13];
    int fm = u_frids_mask[row];
    float at[K_];
#pragma unroll
    for (int k = 0; k < K_; k++) {
        float raw = (k < 5) ? ex[k] : ex[3 + k];
        at[k] = lrelu(du + raw + b4v);
    }
    float mx = -1e30f;
#pragma unroll
    for (int k = 0; k < K_; k++) if (k < fm) mx = fmaxf(mx, at[k]);
    float se = 0.f, ev[K_];
#pragma unroll
    for (int k = 0; k < K_; k++) { ev[k] = (k < fm) ? __expf(at[k] - mx) : 0.f; se += ev[k]; }
    float inv = __fdividef(1.f, se * (float)fm);

    // ---- su partial (own friends), exchange, sum ----
    float spx = 0.f, spy = 0.f;
#pragma unroll
    for (int k5 = 0; k5 < 5; k5++) {
        float wk = ev[kbase + k5] * inv;
        spx = fmaf(wk, px[k5], spx);
        spy = fmaf(wk, py[k5], spy);
    }
    sux[w2 * 64 + c0] = spx;
    sux[w2 * 64 + c0 + 1] = spy;
    asm volatile("bar.sync %0, 64;" :: "r"(barid) : "memory");
    float sufx = sux[c0] + sux[64 + c0];
    float sufy = sux[c0 + 1] + sux[64 + c0 + 1];

    // ---- warp0 builds z pairs (z2,z5) ----
    if (w2 == 0) {
        PACK2(zz[c0],       hu2.x, sufx);
        PACK2(zz[c0 + 1],   hu2.y, sufy);
        PACK2(zz[64 + c0],     ie2.x, ie2.x);
        PACK2(zz[64 + c0 + 1], ie2.y, ie2.y);
        PACK2(zz[128 + c0],     hu2.x * ie2.x, sufx * ie2.x);
        PACK2(zz[128 + c0 + 1], hu2.y * ie2.y, sufy * ie2.y);
    }
    asm volatile("bar.sync %0, 64;" :: "r"(barid) : "memory");

    // ---- fused hui/sui GEMV, split k-range per warp ----
    ull acc0, acc1;
    if (w2 == 0) {
        PACK2(acc0, b2[c0], b5[c0]);
        PACK2(acc1, b2[c0 + 1], b5[c0 + 1]);
    } else { acc0 = 0ull; acc1 = 0ull; }
    const ulonglong2* wip = (const ulonglong2*)&g_wi[4 * lane];
    int kk0 = w2 * 96;
#pragma unroll 8
    for (int k = kk0; k < kk0 + 96; k++) {
        ull zk = zz[k];
        ulonglong2 wv = __ldg(wip + k * 32);
        FMA2(acc0, zk, wv.x, acc0);
        FMA2(acc1, zk, wv.y, acc1);
    }
    accx[w2 * 64 + 2 * lane] = acc0;
    accx[w2 * 64 + 2 * lane + 1] = acc1;
    asm volatile("bar.sync %0, 64;" :: "r"(barid) : "memory");
    float huix, suix, huiy, suiy;
    {
        float a0l, a0h, b0l, b0h, a1l, a1h, b1l, b1h;
        UNPACK2(a0l, a0h, accx[2 * lane]);
        UNPACK2(b0l, b0h, accx[64 + 2 * lane]);
        UNPACK2(a1l, a1h, accx[2 * lane + 1]);
        UNPACK2(b1l, b1h, accx[64 + 2 * lane + 1]);
        huix = a0l + b0l; suix = a0h + b0h;
        huiy = a1l + b1l; suiy = a1h + b1h;
    }

    float zsx = l0 * hu2.x + l1 * huix + l2 * sufx + l3 * suix;
    float zsy = l0 * hu2.y + l1 * huiy + l2 * sufy + l3 * suiy;

    // ---- F_i: each warp handles its own s = w2 ----
    {
        float sp[K_], dp[K_];
#pragma unroll
        for (int k = 0; k < K_; k++) {
            int fi = F_i[(row * 2 + w2) * K_ + k];
            float2 f2 = *(const float2*)(item_emb + fi * 64 + c0);
            sp[k] = f2.x * W6s[64 + c0] + f2.y * W6s[65 + c0];
            dp[k] = f2.x * zsx + f2.y * zsy;
        }
#pragma unroll
        for (int o = 16; o; o >>= 1) {
#pragma unroll
            for (int k = 0; k < K_; k++) {
                sp[k] += __shfl_xor_sync(0xffffffffu, sp[k], o);
                dp[k] += __shfl_xor_sync(0xffffffffu, dp[k], o);
            }
        }
        if (lane == 0) {
            float* spo = w2 ? g_s2 : g_s1;
            float* dpo = w2 ? g_d2 : g_d1;
#pragma unroll
            for (int k = 0; k < K_; k++) {
                spo[k * B_ + row] = lrelu(di + sp[k] + b6v);
                dpo[k * B_ + row] = dp[k];
            }
        }
    }
}

// ============================================================================
// K4: per-column softmax stats (online), coalesced [K][B].
// ============================================================================
__global__ void k_cstat() {
    int sel = blockIdx.x / K_;
    int k = blockIdx.x % K_;
    const float* s = (sel ? g_s2 : g_s1) + k * B_;
    __shared__ float rm[1024], rs[1024];
    int tid = threadIdx.x;
    float m = -1e30f, acc = 0.f;
    for (int i = tid; i < B_; i += 1024) {
        float x = s[i];
        float nm = fmaxf(m, x);
        acc = acc * __expf(m - nm) + __expf(x - nm);
        m = nm;
    }
    rm[tid] = m; rs[tid] = acc;
    __syncthreads();
    for (int o = 512; o; o >>= 1) {
        if (tid < o) {
            float m2 = rm[tid + o], s2v = rs[tid + o];
            float nm = fmaxf(rm[tid], m2);
            rs[tid] = rs[tid] * __expf(rm[tid] - nm) + s2v * __expf(m2 - nm);
            rm[tid] = nm;
        }
        __syncthreads();
    }
    if (tid == 0) { g_cs[sel * 2 * K_ + k] = rm[0]; g_cs[sel * 2 * K_ + K_ + k] = rs[0]; }
}

// ============================================================================
// K5: final S + sigmoid (coalesced [K][B] reads)
// ============================================================================
__global__ void k_final(const float* __restrict__ alpha, float* __restrict__ out) {
    int b = blockIdx.x * 256 + threadIdx.x;
    float a = alpha[0];
    float S1 = 0.f, S2 = 0.f;
#pragma unroll
    for (int k = 0; k < K_; k++) {
        S1 += __expf(g_s1[k * B_ + b] - g_cs[k]) / g_cs[K_ + k] * g_d1[k * B_ + b];
        S2 += __expf(g_s2[k * B_ + b] - g_cs[2 * K_ + k]) / g_cs[3 * K_ + k] * g_d2[k * B_ + b];
    }
    float S = a * S1 + (1.f - a) * S2;
    out[b] = __fdividef(1.f, 1.f + __expf(-S));
}

// ============================================================================
extern "C" void kernel_launch(void* const* d_in, const int* in_sizes, int n_in,
                              void* d_out, int out_size) {
    const int*   users        = (const int*)d_in[0];
    const int*   items        = (const int*)d_in[1];
    const int*   u_items      = (const int*)d_in[2];
    const int*   u_items_mask = (const int*)d_in[3];
    const int*   u_frids      = (const int*)d_in[4];
    const int*   u_frids_mask = (const int*)d_in[5];
    const int*   u_frids_items= (const int*)d_in[6];
    const int*   F_i          = (const int*)d_in[7];
    const float* user_emb     = (const float*)d_in[8];
    const float* item_emb     = (const float*)d_in[9];
    const float* i_class      = (const float*)d_in[10];
    const float* W1  = (const float*)d_in[11];
    const float* b1  = (const float*)d_in[12];
    const float* Wih = (const float*)d_in[13];
    const float* Whh = (const float*)d_in[14];
    const float* bih = (const float*)d_in[15];
    const float* bhh = (const float*)d_in[16];
    const float* W2  = (const float*)d_in[17];
    const float* b2  = (const float*)d_in[18];
    const float* W3  = (const float*)d_in[19];
    const float* b3  = (const float*)d_in[20];
    const float* W4  = (const float*)d_in[21];
    const float* b4  = (const float*)d_in[22];
    const float* W5  = (const float*)d_in[23];
    const float* b5  = (const float*)d_in[24];
    const float* W6  = (const float*)d_in[25];
    const float* b6  = (const float*)d_in[26];
    const float* alpha   = (const float*)d_in[27];
    const float* lambdas = (const float*)d_in[28];

    cudaFuncSetAttribute(k_precompute, cudaFuncAttributeMaxDynamicSharedMemorySize, PRE_SMEM);
    cudaFuncSetAttribute(k_lstm, cudaFuncAttributeMaxDynamicSharedMemorySize, LSTM_SMEM);
    cudaFuncSetAttribute(k_user, cudaFuncAttributeMaxDynamicSharedMemorySize, USER_SMEM);

    k_combine<<<171, 256>>>(W1, b1, Wih, bih, bhh, W2, W5);
    k_sort<<<1, 1024>>>(u_items_mask);
    k_precompute<<<(NIP1 + 63) / 64, 256, PRE_SMEM>>>(item_emb, i_class, W3, b3);
    k_lstm<<<148, 256, LSTM_SMEM>>>(u_items, u_items_mask, Whh);
    k_user<<<B_ / 8, 512, USER_SMEM>>>(users, items, u_frids, u_frids_mask,
                                       u_frids_items, F_i, user_emb, item_emb,
                                       b2, W4, b4, b5, W6, b6, lambdas);
    k_cstat<<<2 * K_, 1024>>>();
    k_final<<<B_ / 256, 256>>>(alpha, (float*)d_out);
}

// round 16
// speedup vs baseline: 1.5709x; 1.0696x over previous
#include <cuda_runtime.h>
#include <math.h>

#define B_   4096
#define L_   50
#define K_   10
#define LI_  20
#define D_   64
#define C_   10
#define NIP1 50001

typedef unsigned long long ull;

// ---------------- scratch (static device globals; no allocation) -------------
__device__ float g_ju1[NIP1 * 256];   // gate-permuted x@Wih with all biases folded
__device__ float g_jv[NIP1 * D_];
__device__ float g_wc[64 * 256];      // (W1[0:64]@Wih) gate-permuted (emb part)
__device__ float g_tblj[C_ * 256];    // class table: W1[64+cls]@Wih + bc (gate-permuted)
__device__ float g_tblv[C_ * 64];     // class table: W3[64+cls] + b3
__device__ float g_wi[192 * 128];     // interleaved (W2[k][c], W5[k][c])
__device__ float g_hu[B_ * D_];
__device__ float g_s1[K_ * B_];       // transposed [K][B]
__device__ float g_s2[K_ * B_];
__device__ float g_d1[K_ * B_];
__device__ float g_d2[K_ * B_];
__device__ float g_cs[4 * K_];
__device__ int   g_order[B_];

__device__ __forceinline__ float lrelu(float x) { return x >= 0.f ? x : 0.01f * x; }

// packed f32x2 fma (FFMA2) — only reachable via PTX
#define FMA2(d, a, b, c) \
    asm("fma.rn.f32x2 %0, %1, %2, %3;" : "=l"(d) : "l"(a), "l"(b), "l"(c))
#define PACK_DUP(d, x) \
    asm("mov.b64 %0, {%1, %1};" : "=l"(d) : "f"(x))
#define PACK2(d, lo, hi) \
    asm("mov.b64 %0, {%1, %2};" : "=l"(d) : "f"(lo), "f"(hi))
#define UNPACK2(lo, hi, p) \
    asm("mov.b64 {%0, %1}, %2;" : "=f"(lo), "=f"(hi) : "l"(p))

__device__ __forceinline__ float sigf(float x) {
    return __fdividef(1.f, 1.f + __expf(-x));
}
__device__ __forceinline__ float tanhf_fast(float x) {
    return 1.f - __fdividef(2.f, __expf(2.f * x) + 1.f);
}

// ============================================================================
// K0: combine. Blocks 0..63: Wc emb rows. Blocks 64..73: class table ju
// (incl. bc fold). Block 74: class table jv. Blocks 75..170: g_wi interleave.
// ============================================================================
__global__ void k_combine(const float* __restrict__ W1, const float* __restrict__ b1,
                          const float* __restrict__ Wih, const float* __restrict__ bih,
                          const float* __restrict__ bhh,
                          const float* __restrict__ W2, const float* __restrict__ W5,
                          const float* __restrict__ W3, const float* __restrict__ b3) {
    int k = blockIdx.x;
    int tid = threadIdx.x;
    if (k < 64) {
        int jp = tid;
        int c = jp >> 2, g = jp & 3;
        int j = c + 64 * g;
        float s = 0.f;
#pragma unroll
        for (int m = 0; m < 64; m++)
            s = fmaf(W1[k * 64 + m], __ldg(&Wih[m * 256 + j]), s);
        g_wc[k * 256 + jp] = s;
    } else if (k < 74) {
        int cls = k - 64;
        int jp = tid;
        int c = jp >> 2, g = jp & 3;
        int j = c + 64 * g;
        float s = bih[j] + bhh[j];
#pragma unroll
        for (int m = 0; m < 64; m++)
            s = fmaf(W1[(64 + cls) * 64 + m] + b1[m], __ldg(&Wih[m * 256 + j]), s);
        g_tblj[cls * 256 + jp] = s;
    } else if (k == 74) {
        for (int i = tid; i < C_ * 64; i += 256) {
            int cls = i >> 6, c = i & 63;
            g_tblv[i] = W3[(64 + cls) * 64 + c] + b3[c];
        }
    } else {
        int idx = (k - 75) * 256 + tid;    // 0 .. 192*128-1
        int kk = idx >> 7, j = idx & 127;
        int c = j >> 1;
        g_wi[idx] = (j & 1) ? W5[kk * 64 + c] : W2[kk * 64 + c];
    }
}

// ============================================================================
// K0b: counting sort of rows by u_items_mask, DESCENDING. (main stream)
// ============================================================================
__global__ void k_sort(const int* __restrict__ mask) {
    __shared__ int cnt[64], off[64];
    int tid = threadIdx.x;
    if (tid < 64) cnt[tid] = 0;
    __syncthreads();
    for (int i = tid; i < B_; i += 1024) atomicAdd(&cnt[mask[i]], 1);
    __syncthreads();
    if (tid == 0) {
        int run = 0;
        for (int m = 50; m >= 1; m--) { off[m] = run; run += cnt[m]; }
    }
    __syncthreads();
    if (tid < 64) cnt[tid] = 0;
    __syncthreads();
    for (int i = tid; i < B_; i += 1024) {
        int m = mask[i];
        int pos = off[m] + atomicAdd(&cnt[m], 1);
        g_order[pos] = i;
    }
}

// ============================================================================
// K1: g_ju1 = item_emb @ Wc + TBLju[cls], g_jv = item_emb @ W3 + TBLv[cls].
// One-hot class folded into acc init; k loop 64 (was 74). 64 rows/block,
// 8 rows/thread. xs stride 68 = conflict-free & float4-aligned.
// ============================================================================
#define PRE_SMEM ((64 * 68 + 64) * 4)

__global__ void __launch_bounds__(256)
k_precompute(const float* __restrict__ item_emb, const float* __restrict__ i_class,
             const float* __restrict__ W3) {
    extern __shared__ float sm[];
    float* xs = sm;                  // 64*68
    int* cls_s = (int*)(xs + 64 * 68);  // 64

    int tid = threadIdx.x;
    int c = tid & 31, rgrp = tid >> 5;
    int row0 = blockIdx.x * 64;

    // stage x (float4-coalesced from item_emb)
    for (int i = tid; i < 64 * 16; i += 256) {
        int rr = i >> 4, q = i & 15;
        int row = row0 + rr;
        float4 v;
        if (row < NIP1) v = __ldg((const float4*)&item_emb[row * 64 + q * 4]);
        else { v.x = 0.f; v.y = 0.f; v.z = 0.f; v.w = 0.f; }
        *(float4*)&xs[rr * 68 + q * 4] = v;
    }
    // class ids
    if (tid < 64) {
        int row = row0 + tid;
        int cc = 0;
        if (row < NIP1) {
#pragma unroll
            for (int j = 0; j < C_; j++)
                if (i_class[row * C_ + j] > 0.5f) cc = j;
        }
        cls_s[tid] = cc;
    }
    __syncthreads();

    ull a[8][4], jv[8];
#pragma unroll
    for (int r = 0; r < 8; r++) {
        int cr = cls_s[rgrp * 8 + r];
        const ull* bp = (const ull*)&g_tblj[cr * 256 + 8 * c];
        a[r][0] = __ldg(bp); a[r][1] = __ldg(bp + 1);
        a[r][2] = __ldg(bp + 2); a[r][3] = __ldg(bp + 3);
        jv[r] = __ldg((const ull*)&g_tblv[cr * 64 + 2 * c]);
    }
#pragma unroll 2
    for (int k = 0; k < 64; k++) {
        const ulonglong2* wp = (const ulonglong2*)&g_wc[k * 256 + 8 * c];
        ulonglong2 wa = __ldg(wp), wb = __ldg(wp + 1);
        ull w3v = __ldg((const ull*)&W3[k * 64 + 2 * c]);
        const float* xr = &xs[(rgrp * 8) * 68 + k];
#pragma unroll
        for (int r = 0; r < 8; r++) {
            float av = xr[r * 68];
            ull ad; PACK_DUP(ad, av);
            FMA2(a[r][0], ad, wa.x, a[r][0]);
            FMA2(a[r][1], ad, wa.y, a[r][1]);
            FMA2(a[r][2], ad, wb.x, a[r][2]);
            FMA2(a[r][3], ad, wb.y, a[r][3]);
            FMA2(jv[r], ad, w3v, jv[r]);
        }
    }
#pragma unroll
    for (int r = 0; r < 8; r++) {
        int row = row0 + rgrp * 8 + r;
        if (row < NIP1) {
            ull* o = (ull*)&g_ju1[row * 256 + 8 * c];
            o[0] = a[r][0]; o[1] = a[r][1]; o[2] = a[r][2]; o[3] = a[r][3];
            *(ull*)&g_jv[row * 64 + 2 * c] = jv[r];
        }
    }
}

// ============================================================================
// K2: PAIR-SPLIT LSTM (round-13 validated, ~108us). Unchanged.
// ============================================================================
#define LSTM_PFL (512 + 200 + 8)   // per-pair floats: hbuf x2 (2x256) + idxs + pad
#define LSTM_SMEM ((64*256 + 4*LSTM_PFL) * 4)

__global__ void __launch_bounds__(256, 1)
k_lstm(const int* __restrict__ u_items, const int* __restrict__ u_items_mask,
       const float* __restrict__ Whh) {
    extern __shared__ float sm[];
    float* Wp = sm;                               // 64*256 gate-permuted Whh
    int tid = threadIdx.x;
    int wid = tid >> 5, lane = tid & 31;
    int pid = wid >> 1;                           // pair 0..3
    int half = wid & 1;                           // cell half
    float* hbuf = Wp + 64 * 256 + pid * LSTM_PFL; // 2 x 256 (layout [cell][row])
    int*   idxs = (int*)(hbuf + 512);             // 4*50

    for (int i = tid; i < 64 * 256; i += 256) {
        int k = i >> 8, jp = i & 255;
        Wp[i] = Whh[k * 256 + (jp >> 2) + 64 * (jp & 3)];
    }
    __syncthreads();   // the only block-wide barrier

    int cell = half * 32 + lane;
    int p = pid * 148 + blockIdx.x;               // pair id 0..591
    const float* WpL = Wp + cell * 4;

#pragma unroll 1
    for (int ci = 0; ci < 2; ci++) {
        int chunk = ci ? (1183 - p) : p;
        if (chunk > 1023) continue;

        int rows[4], msk[4];
#pragma unroll
        for (int r = 0; r < 4; r++) {
            rows[r] = g_order[chunk * 4 + r];
            msk[r] = u_items_mask[rows[r]];
        }
        int maxm = msk[0];

        for (int i = lane; i < 100; i += 32) {
            int r = 2 * half + i / 50, t = i % 50;
            idxs[r * 50 + t] = u_items[rows[r] * 50 + t];
        }
        {
            float4 z4; z4.x = 0.f; z4.y = 0.f; z4.z = 0.f; z4.w = 0.f;
            *(float4*)&hbuf[cell * 4] = z4;
        }
        asm volatile("bar.sync %0, 64;" :: "r"(pid + 1) : "memory");

        float c_reg[4];
#pragma unroll
        for (int r = 0; r < 4; r++) c_reg[r] = 0.f;

        float4 p4[4];
#pragma unroll
        for (int r = 0; r < 4; r++)
            p4[r] = *(const float4*)&g_ju1[idxs[r * 50] * 256 + cell * 4];

        for (int t = 0; t < maxm; t++) {
            const float* hr = hbuf + (t & 1) * 256;
            float* hw = hbuf + ((t + 1) & 1) * 256;

            ull acc[4][2];
            PACK2(acc[0][0], p4[0].x, p4[1].x); PACK2(acc[0][1], p4[2].x, p4[3].x);
            PACK2(acc[1][0], p4[0].y, p4[1].y); PACK2(acc[1][1], p4[2].y, p4[3].y);
            PACK2(acc[2][0], p4[0].z, p4[1].z); PACK2(acc[2][1], p4[2].z, p4[3].z);
            PACK2(acc[3][0], p4[0].w, p4[1].w); PACK2(acc[3][1], p4[2].w, p4[3].w);

            if (t + 1 < maxm) {
#pragma unroll
                for (int r = 0; r < 4; r++)
                    p4[r] = *(const float4*)&g_ju1[idxs[r * 50 + t + 1] * 256 + cell * 4];
            }

            float4 nw = *(const float4*)&WpL[0];
            float4 nh = *(const float4*)&hr[0];
#pragma unroll 8
            for (int k = 0; k < 64; k++) {
                float4 w = nw;
                float4 h = nh;
                int kn = (k + 1) & 63;
                nw = *(const float4*)&WpL[kn * 256];
                nh = *(const float4*)&hr[kn * 4];
                ull h01, h23, d;
                PACK2(h01, h.x, h.y);
                PACK2(h23, h.z, h.w);
                PACK_DUP(d, w.x); FMA2(acc[0][0], h01, d, acc[0][0]); FMA2(acc[0][1], h23, d, acc[0][1]);
                PACK_DUP(d, w.y); FMA2(acc[1][0], h01, d, acc[1][0]); FMA2(acc[1][1], h23, d, acc[1][1]);
                PACK_DUP(d, w.z); FMA2(acc[2][0], h01, d, acc[2][0]); FMA2(acc[2][1], h23, d, acc[2][1]);
                PACK_DUP(d, w.w); FMA2(acc[3][0], h01, d, acc[3][0]); FMA2(acc[3][1], h23, d, acc[3][1]);
            }

            float hval[4];
#pragma unroll
            for (int rp = 0; rp < 2; rp++) {
                float gi0, gi1, gf0, gf1, gg0, gg1, go0, go1;
                UNPACK2(gi0, gi1, acc[0][rp]);
                UNPACK2(gf0, gf1, acc[1][rp]);
                UNPACK2(gg0, gg1, acc[2][rp]);
                UNPACK2(go0, go1, acc[3][rp]);
#pragma unroll
                for (int h2 = 0; h2 < 2; h2++) {
                    int r = 2 * rp + h2;
                    float gi = h2 ? gi1 : gi0;
                    float gf = h2 ? gf1 : gf0;
                    float gg = h2 ? gg1 : gg0;
                    float go = h2 ? go1 : go0;
                    float cc = sigf(gf) * c_reg[r] + sigf(gi) * tanhf_fast(gg);
                    c_reg[r] = cc;
                    hval[r] = sigf(go) * tanhf_fast(cc);
                }
            }
            float4 hv4;
            hv4.x = hval[0]; hv4.y = hval[1]; hv4.z = hval[2]; hv4.w = hval[3];
            *(float4*)&hw[cell * 4] = hv4;

#pragma unroll
            for (int r = 0; r < 4; r++) {
                if (t == msk[r] - 1)
                    g_hu[rows[r] * 64 + cell] = hval[r];
            }
            asm volatile("bar.sync %0, 64;" :: "r"(pid + 1) : "memory");
        }
    }
}

// ============================================================================
// K3: PAIR-SPLIT user stage (round-14 validated). Unchanged.
// ============================================================================
#define USER_ROWF 784
#define USER_SMEM ((256 + 8 * USER_ROWF) * 4)

__global__ void __launch_bounds__(512)
k_user(const int* __restrict__ users, const int* __restrict__ items,
       const int* __restrict__ u_frids, const int* __restrict__ u_frids_mask,
       const int* __restrict__ u_frids_items, const int* __restrict__ F_i,
       const float* __restrict__ user_emb, const float* __restrict__ item_emb,
       const float* __restrict__ b2,
       const float* __restrict__ W4, const float* __restrict__ b4,
       const float* __restrict__ b5,
       const float* __restrict__ W6, const float* __restrict__ b6,
       const float* __restrict__ lambdas) {
    extern __shared__ float sm[];
    float* W4s = sm;                  // 128
    float* W6s = W4s + 128;           // 128
    float* rowbuf = W6s + 128;        // 8 * USER_ROWF

    int tid = threadIdx.x;
    if (tid < 128) W4s[tid] = W4[tid];
    else if (tid < 256) W6s[tid - 128] = W6[tid - 128];
    __syncthreads();

    int rp = tid >> 6;
    int w2 = (tid >> 5) & 1;
    int lane = tid & 31;
    int row = blockIdx.x * 8 + rp;
    int c0 = lane * 2;
    int barid = rp + 1;
    float* rb  = rowbuf + rp * USER_ROWF;
    float* ex  = rb;
    float* sux = rb + 16;
    ull*  zz   = (ull*)(rb + 144);
    ull*  accx = (ull*)(rb + 528);

    float l0 = lambdas[0], l1 = lambdas[1], l2 = lambdas[2], l3 = lambdas[3];
    float b4v = b4[0], b6v = b6[0];

    int usr = users[row], itm = items[row];
    float2 ie2 = *(const float2*)(item_emb + itm * 64 + c0);
    float2 hu2 = *(const float2*)(g_hu + row * 64 + c0);

    int kbase = w2 * 5;
    float px[5], py[5];
#pragma unroll
    for (int k5 = 0; k5 < 5; k5++) { px[k5] = 0.f; py[k5] = 0.f; }
    const int* ip = u_frids_items + (row * K_ + kbase) * LI_;
#pragma unroll
    for (int k5 = 0; k5 < 5; k5++) {
#pragma unroll
        for (int li = 0; li < LI_; li++) {
            int idx = ip[k5 * LI_ + li];
            float2 j2 = *(const float2*)(g_jv + idx * 64 + c0);
            px[k5] += j2.x; py[k5] += j2.y;
        }
    }

    float v0;
    if (w2 == 0) {
        float2 u2 = *(const float2*)(user_emb + usr * 64 + c0);
        v0 = u2.x * W4s[c0] + u2.y * W4s[c0 + 1];
    } else {
        v0 = ie2.x * W6s[c0] + ie2.y * W6s[c0 + 1];
    }
    float at_p[5];
#pragma unroll
    for (int k5 = 0; k5 < 5; k5++) {
        int fid = u_frids[row * K_ + kbase + k5];
        float2 vv = *(const float2*)(user_emb + fid * 64 + c0);
        at_p[k5] = vv.x * W4s[64 + c0] + vv.y * W4s[65 + c0];
    }
#pragma unroll
    for (int o = 16; o; o >>= 1) {
        v0 += __shfl_xor_sync(0xffffffffu, v0, o);
#pragma unroll
        for (int k5 = 0; k5 < 5; k5++)
            at_p[k5] += __shfl_xor_sync(0xffffffffu, at_p[k5], o);
    }
    if (lane == 0) {
#pragma unroll
        for (int k5 = 0; k5 < 5; k5++) ex[w2 * 8 + k5] = at_p[k5];
        ex[w2 * 8 + 5] = v0;
    }
    asm volatile("bar.sync %0, 64;" :: "r"(barid) : "memory");

    float du = ex[5];
    float di = ex[13];
    int fm = u_frids_mask[row];
    float at[K_];
#pragma unroll
    for (int k = 0; k < K_; k++) {
        float raw = (k < 5) ? ex[k] : ex[3 + k];
        at[k] = lrelu(du + raw + b4v);
    }
    float mx = -1e30f;
#pragma unroll
    for (int k = 0; k < K_; k++) if (k < fm) mx = fmaxf(mx, at[k]);
    float se = 0.f, ev[K_];
#pragma unroll
    for (int k = 0; k < K_; k++) { ev[k] = (k < fm) ? __expf(at[k] - mx) : 0.f; se += ev[k]; }
    float inv = __fdividef(1.f, se * (float)fm);

    float spx = 0.f, spy = 0.f;
#pragma unroll
    for (int k5 = 0; k5 < 5; k5++) {
        float wk = ev[kbase + k5] * inv;
        spx = fmaf(wk, px[k5], spx);
        spy = fmaf(wk, py[k5], spy);
    }
    sux[w2 * 64 + c0] = spx;
    sux[w2 * 64 + c0 + 1] = spy;
    asm volatile("bar.sync %0, 64;" :: "r"(barid) : "memory");
    float sufx = sux[c0] + sux[64 + c0];
    float sufy = sux[c0 + 1] + sux[64 + c0 + 1];

    if (w2 == 0) {
        PACK2(zz[c0],       hu2.x, sufx);
        PACK2(zz[c0 + 1],   hu2.y, sufy);
        PACK2(zz[64 + c0],     ie2.x, ie2.x);
        PACK2(zz[64 + c0 + 1], ie2.y, ie2.y);
        PACK2(zz[128 + c0],     hu2.x * ie2.x, sufx * ie2.x);
        PACK2(zz[128 + c0 + 1], hu2.y * ie2.y, sufy * ie2.y);
    }
    asm volatile("bar.sync %0, 64;" :: "r"(barid) : "memory");

    ull acc0, acc1;
    if (w2 == 0) {
        PACK2(acc0, b2[c0], b5[c0]);
        PACK2(acc1, b2[c0 + 1], b5[c0 + 1]);
    } else { acc0 = 0ull; acc1 = 0ull; }
    const ulonglong2* wip = (const ulonglong2*)&g_wi[4 * lane];
    int kk0 = w2 * 96;
#pragma unroll 8
    for (int k = kk0; k < kk0 + 96; k++) {
        ull zk = zz[k];
        ulonglong2 wv = __ldg(wip + k * 32);
        FMA2(acc0, zk, wv.x, acc0);
        FMA2(acc1, zk, wv.y, acc1);
    }
    accx[w2 * 64 + 2 * lane] = acc0;
    accx[w2 * 64 + 2 * lane + 1] = acc1;
    asm volatile("bar.sync %0, 64;" :: "r"(barid) : "memory");
    float huix, suix, huiy, suiy;
    {
        float a0l, a0h, b0l, b0h, a1l, a1h, b1l, b1h;
        UNPACK2(a0l, a0h, accx[2 * lane]);
        UNPACK2(b0l, b0h, accx[64 + 2 * lane]);
        UNPACK2(a1l, a1h, accx[2 * lane + 1]);
        UNPACK2(b1l, b1h, accx[64 + 2 * lane + 1]);
        huix = a0l + b0l; suix = a0h + b0h;
        huiy = a1l + b1l; suiy = a1h + b1h;
    }

    float zsx = l0 * hu2.x + l1 * huix + l2 * sufx + l3 * suix;
    float zsy = l0 * hu2.y + l1 * huiy + l2 * sufy + l3 * suiy;

    {
        float sp[K_], dp[K_];
#pragma unroll
        for (int k = 0; k < K_; k++) {
            int fi = F_i[(row * 2 + w2) * K_ + k];
            float2 f2 = *(const float2*)(item_emb + fi * 64 + c0);
            sp[k] = f2.x * W6s[64 + c0] + f2.y * W6s[65 + c0];
            dp[k] = f2.x * zsx + f2.y * zsy;
        }
#pragma unroll
        for (int o = 16; o; o >>= 1) {
#pragma unroll
            for (int k = 0; k < K_; k++) {
                sp[k] += __shfl_xor_sync(0xffffffffu, sp[k], o);
                dp[k] += __shfl_xor_sync(0xffffffffu, dp[k], o);
            }
        }
        if (lane == 0) {
            float* spo = w2 ? g_s2 : g_s1;
            float* dpo = w2 ? g_d2 : g_d1;
#pragma unroll
            for (int k = 0; k < K_; k++) {
                spo[k * B_ + row] = lrelu(di + sp[k] + b6v);
                dpo[k * B_ + row] = dp[k];
            }
        }
    }
}

// ============================================================================
// K4: per-column softmax stats (online), coalesced [K][B].
// ============================================================================
__global__ void k_cstat() {
    int sel = blockIdx.x / K_;
    int k = blockIdx.x % K_;
    const float* s = (sel ? g_s2 : g_s1) + k * B_;
    __shared__ float rm[1024], rs[1024];
    int tid = threadIdx.x;
    float m = -1e30f, acc = 0.f;
    for (int i = tid; i < B_; i += 1024) {
        float x = s[i];
        float nm = fmaxf(m, x);
        acc = acc * __expf(m - nm) + __expf(x - nm);
        m = nm;
    }
    rm[tid] = m; rs[tid] = acc;
    __syncthreads();
    for (int o = 512; o; o >>= 1) {
        if (tid < o) {
            float m2 = rm[tid + o], s2v = rs[tid + o];
            float nm = fmaxf(rm[tid], m2);
            rs[tid] = rs[tid] * __expf(rm[tid] - nm) + s2v * __expf(m2 - nm);
            rm[tid] = nm;
        }
        __syncthreads();
    }
    if (tid == 0) { g_cs[sel * 2 * K_ + k] = rm[0]; g_cs[sel * 2 * K_ + K_ + k] = rs[0]; }
}

// ============================================================================
// K5: final S + sigmoid (coalesced [K][B] reads)
// ============================================================================
__global__ void k_final(const float* __restrict__ alpha, float* __restrict__ out) {
    int b = blockIdx.x * 256 + threadIdx.x;
    float a = alpha[0];
    float S1 = 0.f, S2 = 0.f;
#pragma unroll
    for (int k = 0; k < K_; k++) {
        S1 += __expf(g_s1[k * B_ + b] - g_cs[k]) / g_cs[K_ + k] * g_d1[k * B_ + b];
        S2 += __expf(g_s2[k * B_ + b] - g_cs[2 * K_ + k]) / g_cs[3 * K_ + k] * g_d2[k * B_ + b];
    }
    float S = a * S1 + (1.f - a) * S2;
    out[b] = __fdividef(1.f, 1.f + __expf(-S));
}

// ============================================================================
extern "C" void kernel_launch(void* const* d_in, const int* in_sizes, int n_in,
                              void* d_out, int out_size) {
    const int*   users        = (const int*)d_in[0];
    const int*   items        = (const int*)d_in[1];
    const int*   u_items      = (const int*)d_in[2];
    const int*   u_items_mask = (const int*)d_in[3];
    const int*   u_frids      = (const int*)d_in[4];
    const int*   u_frids_mask = (const int*)d_in[5];
    const int*   u_frids_items= (const int*)d_in[6];
    const int*   F_i          = (const int*)d_in[7];
    const float* user_emb     = (const float*)d_in[8];
    const float* item_emb     = (const float*)d_in[9];
    const float* i_class      = (const float*)d_in[10];
    const float* W1  = (const float*)d_in[11];
    const float* b1  = (const float*)d_in[12];
    const float* Wih = (const float*)d_in[13];
    const float* Whh = (const float*)d_in[14];
    const float* bih = (const float*)d_in[15];
    const float* bhh = (const float*)d_in[16];
    const float* W2  = (const float*)d_in[17];
    const float* b2  = (const float*)d_in[18];
    const float* W3  = (const float*)d_in[19];
    const float* b3  = (const float*)d_in[20];
    const float* W4  = (const float*)d_in[21];
    const float* b4  = (const float*)d_in[22];
    const float* W5  = (const float*)d_in[23];
    const float* b5  = (const float*)d_in[24];
    const float* W6  = (const float*)d_in[25];
    const float* b6  = (const float*)d_in[26];
    const float* alpha   = (const float*)d_in[27];
    const float* lambdas = (const float*)d_in[28];

    cudaFuncSetAttribute(k_precompute, cudaFuncAttributeMaxDynamicSharedMemorySize, PRE_SMEM);
    cudaFuncSetAttribute(k_lstm, cudaFuncAttributeMaxDynamicSharedMemorySize, LSTM_SMEM);
    cudaFuncSetAttribute(k_user, cudaFuncAttributeMaxDynamicSharedMemorySize, USER_SMEM);

    k_combine<<<171, 256>>>(W1, b1, Wih, bih, bhh, W2, W5, W3, b3);
    k_sort<<<1, 1024>>>(u_items_mask);
    k_precompute<<<(NIP1 + 63) / 64, 256, PRE_SMEM>>>(item_emb, i_class, W3);
    k_lstm<<<148, 256, LSTM_SMEM>>>(u_items, u_items_mask, Whh);
    k_user<<<B_ / 8, 512, USER_SMEM>>>(users, items, u_frids, u_frids_mask,
                                       u_frids_items, F_i, user_emb, item_emb,
                                       b2, W4, b4, b5, W6, b6, lambdas);
    k_cstat<<<2 * K_, 1024>>>();
    k_final<<<B_ / 256, 256>>>(alpha, (float*)d_out);
}